// round 4
// baseline (speedup 1.0000x reference)
#include <cuda_runtime.h>
#include <cuda_bf16.h>
#include <cstdint>

#define EPS 1e-6f

// ---------------- scratch (__device__ globals; no allocations allowed) -----
__device__ float g_q[16777216];            // (16384, 1024) fp32
__device__ float g_k[16777216];
__device__ float g_v[16777216];
__device__ float g_y[16777216];
__device__ float g_kmean[4096];
__device__ float g_kv[262144];
__device__ __nv_bfloat16 g_ahi[16777216];  // A-side hi/lo bf16 (x, later y=att+conv)
__device__ __nv_bfloat16 g_alo[16777216];
__device__ __nv_bfloat16 g_whi[4194304];   // transposed weights hi/lo bf16
__device__ __nv_bfloat16 g_wlo[4194304];   // [Wq_t | Wkv_t | Wproj_t]

// ---------------- PTX helpers (baseline sm_80+ features only) --------------
__device__ __forceinline__ uint32_t smem_u32(const void* p) {
    uint32_t a;
    asm("{ .reg .u64 t; cvta.to.shared.u64 t, %1; cvt.u32.u64 %0, t; }"
        : "=r"(a) : "l"(p));
    return a;
}
__device__ __forceinline__ void cpa16(uint32_t s, const void* g) {
    asm volatile("cp.async.cg.shared.global [%0], [%1], 16;" :: "r"(s), "l"(g));
}
__device__ __forceinline__ void ldmx4(uint32_t* r, uint32_t a) {
    asm volatile("ldmatrix.sync.aligned.m8n8.x4.shared.b16 {%0,%1,%2,%3}, [%4];"
                 : "=r"(r[0]), "=r"(r[1]), "=r"(r[2]), "=r"(r[3]) : "r"(a));
}
__device__ __forceinline__ void mma16816(float* c, const uint32_t* a,
                                         uint32_t b0, uint32_t b1) {
    asm volatile(
        "mma.sync.aligned.m16n8k16.row.col.f32.bf16.bf16.f32 "
        "{%0,%1,%2,%3},{%4,%5,%6,%7},{%8,%9},{%0,%1,%2,%3};"
        : "+f"(c[0]), "+f"(c[1]), "+f"(c[2]), "+f"(c[3])
        : "r"(a[0]), "r"(a[1]), "r"(a[2]), "r"(a[3]), "r"(b0), "r"(b1));
}
#define SWZ64(o) ((o) ^ (((o) >> 3) & 0x30))

// ---------------------------------------------------------------------------
// bf16 split GEMM via mma.sync: D(fp32) = Ahi*Bhi + Ahi*Blo + Alo*Bhi
// CTA tile 256x128, BK=32, 512 threads (16 warps: 4m x 4n, warp tile 64x32),
// 4-stage cp.async ring, 1 __syncthreads per K-chunk.
// epi 0: qkv split — column group g=gn>>10: 0->Oq relu+eps, 1->Ok relu+eps,
//        2->Ov raw. epi 1: +bias -> Oq. Output leading dim = 1024.
// ---------------------------------------------------------------------------
#define BK 32
#define A_STG 16384             // 256x32 bf16
#define B_STG 8192              // 128x32 bf16
#define STG (2 * A_STG + 2 * B_STG)   // 48KB: Ahi|Alo|Bhi|Blo
#define NSTAGE 4

__global__ __launch_bounds__(512, 1)
void mma_gemm(const __nv_bfloat16* __restrict__ Ahi,
              const __nv_bfloat16* __restrict__ Alo,
              const __nv_bfloat16* __restrict__ Bhi,
              const __nv_bfloat16* __restrict__ Blo,
              float* __restrict__ Oq, float* __restrict__ Ok,
              float* __restrict__ Ov, const float* __restrict__ bias, int epi)
{
    extern __shared__ __align__(1024) char smraw[];
    const uint32_t sb = smem_u32(smraw);

    const int tid = threadIdx.x;
    const int wid = tid >> 5, lid = tid & 31;
    const int bm = blockIdx.y, bn = blockIdx.x;

    const int wm = (wid & 3) * 64;    // 4 warps along m
    const int wn = (wid >> 2) * 32;   // 4 warps along n
    const int lr = lid & 15, lc = lid >> 4;

    float acc[4][4][4];
    #pragma unroll
    for (int i = 0; i < 4; ++i)
        #pragma unroll
        for (int j = 0; j < 4; ++j)
            #pragma unroll
            for (int r = 0; r < 4; ++r) acc[i][j][r] = 0.f;

    auto load_stage = [&](int kc, int st) {
        const uint32_t base = sb + st * STG;
        const int kofs = kc * BK;
        // A hi/lo: 1024 16B-chunks each (256 rows x 4 chunks)
        #pragma unroll
        for (int i = 0; i < 2; ++i) {
            const int idx = i * 512 + tid;
            const int r = idx >> 2, c = idx & 3;
            const size_t go = (size_t)(bm * 256 + r) * 1024 + kofs + c * 8;
            const uint32_t so = SWZ64(r * 64 + c * 16);
            cpa16(base + so, Ahi + go);
            cpa16(base + A_STG + so, Alo + go);
        }
        // B hi/lo: 512 chunks each (128 rows x 4 chunks)
        {
            const int r = tid >> 2, c = tid & 3;
            const size_t go = (size_t)(bn * 128 + r) * 1024 + kofs + c * 8;
            const uint32_t so = SWZ64(r * 64 + c * 16);
            cpa16(base + 2 * A_STG + so, Bhi + go);
            cpa16(base + 2 * A_STG + B_STG + so, Blo + go);
        }
        asm volatile("cp.async.commit_group;" ::: "memory");
    };

    auto compute = [&](int st) {
        const uint32_t base = sb + st * STG;
        #pragma unroll
        for (int ks = 0; ks < 2; ++ks) {
            uint32_t bh[2][4], bl[2][4];
            #pragma unroll
            for (int nj = 0; nj < 2; ++nj) {
                uint32_t off = SWZ64((wn + nj * 16 + lr) * 64 + (ks * 2 + lc) * 16);
                ldmx4(bh[nj], base + 2 * A_STG + off);
                ldmx4(bl[nj], base + 2 * A_STG + B_STG + off);
            }
            uint32_t af[4][4];
            // pass 1+2: Ahi * (Bhi, Blo)
            #pragma unroll
            for (int mi = 0; mi < 4; ++mi) {
                uint32_t off = SWZ64((wm + mi * 16 + lr) * 64 + (ks * 2 + lc) * 16);
                ldmx4(af[mi], base + off);
            }
            #pragma unroll
            for (int mi = 0; mi < 4; ++mi)
                #pragma unroll
                for (int ni = 0; ni < 4; ++ni) {
                    const int nj = ni >> 1, s = ni & 1;
                    mma16816(acc[mi][ni], af[mi], bh[nj][s], bh[nj][s + 2]);
                    mma16816(acc[mi][ni], af[mi], bl[nj][s], bl[nj][s + 2]);
                }
            // pass 3: Alo * Bhi (reuse frag regs)
            #pragma unroll
            for (int mi = 0; mi < 4; ++mi) {
                uint32_t off = SWZ64((wm + mi * 16 + lr) * 64 + (ks * 2 + lc) * 16);
                ldmx4(af[mi], base + A_STG + off);
            }
            #pragma unroll
            for (int mi = 0; mi < 4; ++mi)
                #pragma unroll
                for (int ni = 0; ni < 4; ++ni) {
                    const int nj = ni >> 1, s = ni & 1;
                    mma16816(acc[mi][ni], af[mi], bh[nj][s], bh[nj][s + 2]);
                }
        }
    };

    // prologue: 3 stages in flight
    load_stage(0, 0);
    load_stage(1, 1);
    load_stage(2, 2);

    const int NK = 1024 / BK;   // 32
    for (int kc = 0; kc < NK; ++kc) {
        if (kc < NK - 2)
            asm volatile("cp.async.wait_group 2;" ::: "memory");
        else if (kc == NK - 2)
            asm volatile("cp.async.wait_group 1;" ::: "memory");
        else
            asm volatile("cp.async.wait_group 0;" ::: "memory");
        __syncthreads();
        if (kc + 3 < NK) load_stage(kc + 3, (kc + 3) & (NSTAGE - 1));
        compute(kc & (NSTAGE - 1));
    }

    // ---------------- epilogue ----------------
    const int qrow = lid >> 2;
    const int qcol = (lid & 3) * 2;
    // entire CTA lies in one 1024-column group (128 | 1024)
    const int g = (bn * 128) >> 10;
    float* Obase = (epi == 1) ? Oq : (g == 0 ? Oq : (g == 1 ? Ok : Ov));
    const bool do_relu = (epi == 0) && (g < 2);
    const int ncol0 = (epi == 1) ? bn * 128 : (bn * 128) & 1023;

    #pragma unroll
    for (int mi = 0; mi < 4; ++mi) {
        #pragma unroll
        for (int ni = 0; ni < 4; ++ni) {
            const int cn = ncol0 + wn + ni * 8 + qcol;
            #pragma unroll
            for (int half = 0; half < 2; ++half) {
                const int gm = bm * 256 + wm + mi * 16 + qrow + half * 8;
                float v0 = acc[mi][ni][half * 2 + 0];
                float v1 = acc[mi][ni][half * 2 + 1];
                if (epi == 1) {
                    const float2 bb = *(const float2*)(bias + cn);
                    v0 += bb.x; v1 += bb.y;
                } else if (do_relu) {
                    v0 = fmaxf(v0, 0.f) + EPS;
                    v1 = fmaxf(v1, 0.f) + EPS;
                }
                *(float2*)(Obase + (size_t)gm * 1024 + cn) = make_float2(v0, v1);
            }
        }
    }
}

// ---------------------------------------------------------------------------
// hi/lo bf16 split of an fp32 array (vectorized by 4)
// ---------------------------------------------------------------------------
__global__ void asplit(const float4* __restrict__ X,
                       __nv_bfloat162* __restrict__ Hi,
                       __nv_bfloat162* __restrict__ Lo, int n4)
{
    int i = blockIdx.x * 256 + threadIdx.x;
    if (i >= n4) return;
    float4 v = X[i];
    __nv_bfloat16 h0 = __float2bfloat16(v.x), h1 = __float2bfloat16(v.y);
    __nv_bfloat16 h2 = __float2bfloat16(v.z), h3 = __float2bfloat16(v.w);
    __nv_bfloat16 l0 = __float2bfloat16(v.x - __bfloat162float(h0));
    __nv_bfloat16 l1 = __float2bfloat16(v.y - __bfloat162float(h1));
    __nv_bfloat16 l2 = __float2bfloat16(v.z - __bfloat162float(h2));
    __nv_bfloat16 l3 = __float2bfloat16(v.w - __bfloat162float(h3));
    Hi[2 * i]     = __halves2bfloat162(h0, h1);
    Hi[2 * i + 1] = __halves2bfloat162(h2, h3);
    Lo[2 * i]     = __halves2bfloat162(l0, l1);
    Lo[2 * i + 1] = __halves2bfloat162(l2, l3);
}

// ---------------------------------------------------------------------------
// transpose + hi/lo split of weight W[K,N] -> T[N,K] bf16
// ---------------------------------------------------------------------------
__global__ void wtsplit(const float* __restrict__ W,
                        __nv_bfloat16* __restrict__ Thi,
                        __nv_bfloat16* __restrict__ Tlo, int K, int N)
{
    __shared__ float t[32][33];
    const int n0 = blockIdx.x * 32, k0 = blockIdx.y * 32;
    const int tx = threadIdx.x, ty = threadIdx.y;
    #pragma unroll
    for (int i = 0; i < 32; i += 8)
        t[ty + i][tx] = W[(size_t)(k0 + ty + i) * N + n0 + tx];
    __syncthreads();
    #pragma unroll
    for (int i = 0; i < 32; i += 8) {
        float v = t[tx][ty + i];
        __nv_bfloat16 h = __float2bfloat16(v);
        __nv_bfloat16 l = __float2bfloat16(v - __bfloat162float(h));
        Thi[(size_t)(n0 + ty + i) * K + k0 + tx] = h;
        Tlo[(size_t)(n0 + ty + i) * K + k0 + tx] = l;
    }
}

// ---------------------------------------------------------------------------
// kv[b,h,d,e] = (1/4096) sum_n k[b,n,h,d]*v[b,n,h,e]; also fused
// km[b,h*64+d] += (1/4096) sum_n k[b,n,h,d].  grid (16 nc, 16 h, 4 b).
// ---------------------------------------------------------------------------
__global__ __launch_bounds__(256)
void kvmat_kernel(const float* __restrict__ k, const float* __restrict__ v,
                  float* __restrict__ kv, float* __restrict__ km)
{
    __shared__ float Ks[32][64];
    __shared__ float Vs[32][64];
    __shared__ float sks[4][64];
    const int tid = threadIdx.x;
    const int nc = blockIdx.x, h = blockIdx.y, b = blockIdx.z;
    const int lr = tid >> 4;
    const int lc = (tid & 15) << 2;
    const int tr = (tid >> 4) << 2;
    const int tc = (tid & 15) << 2;
    const int sd = tid & 63;          // ksum channel
    const int sg = tid >> 6;          // ksum row group (8 rows each)

    float acc[4][4];
    #pragma unroll
    for (int i = 0; i < 4; ++i)
        #pragma unroll
        for (int j = 0; j < 4; ++j) acc[i][j] = 0.f;
    float ks_acc = 0.f;

    const size_t base = ((size_t)(b * 4096 + nc * 256)) * 1024 + h * 64;
    for (int t = 0; t < 256; t += 32) {
        const float* kp = k + base + (size_t)(t + lr) * 1024 + lc;
        const float* vp = v + base + (size_t)(t + lr) * 1024 + lc;
        *(float4*)&Ks[lr][lc]      = *(const float4*)kp;
        *(float4*)&Ks[lr + 16][lc] = *(const float4*)(kp + (size_t)16 * 1024);
        *(float4*)&Vs[lr][lc]      = *(const float4*)vp;
        *(float4*)&Vs[lr + 16][lc] = *(const float4*)(vp + (size_t)16 * 1024);
        __syncthreads();
        #pragma unroll
        for (int nn = 0; nn < 32; ++nn) {
            float a[4], bb[4];
            *(float4*)a  = *(const float4*)&Ks[nn][tr];
            *(float4*)bb = *(const float4*)&Vs[nn][tc];
            #pragma unroll
            for (int i = 0; i < 4; ++i)
                #pragma unroll
                for (int j = 0; j < 4; ++j)
                    acc[i][j] = fmaf(a[i], bb[j], acc[i][j]);
        }
        #pragma unroll
        for (int rr = 0; rr < 8; ++rr)
            ks_acc += Ks[sg * 8 + rr][sd];
        __syncthreads();
    }
    sks[sg][sd] = ks_acc;
    __syncthreads();
    if (tid < 64)
        atomicAdd(&km[b * 1024 + h * 64 + tid],
                  (sks[0][tid] + sks[1][tid] + sks[2][tid] + sks[3][tid]) *
                      (1.0f / 4096.0f));
    #pragma unroll
    for (int i = 0; i < 4; ++i)
        #pragma unroll
        for (int j = 0; j < 4; ++j)
            atomicAdd(&kv[(size_t)((b * 16 + h) * 64 + tr + i) * 64 + tc + j],
                      acc[i][j] * (1.0f / 4096.0f));
}

// ---------------------------------------------------------------------------
// att -> y (writes '=')
// ---------------------------------------------------------------------------
__global__ __launch_bounds__(128)
void att_kernel(const float* __restrict__ q, const float* __restrict__ kvm,
                const float* __restrict__ km, float* __restrict__ y)
{
    __shared__ float kvs[64][64];
    __shared__ float kms[64];
    const int b = blockIdx.z, h = blockIdx.y;
    const int n = blockIdx.x * 128 + threadIdx.x;

    const float* kvp = kvm + (size_t)(b * 16 + h) * 4096;
    for (int i = threadIdx.x; i < 1024; i += 128)
        ((float4*)kvs)[i] = ((const float4*)kvp)[i];
    if (threadIdx.x < 16)
        ((float4*)kms)[threadIdx.x] =
            ((const float4*)(km + b * 1024 + h * 64))[threadIdx.x];
    __syncthreads();

    const size_t off = ((size_t)(b * 4096 + n)) * 1024 + h * 64;
    float qr[64];
    #pragma unroll
    for (int i = 0; i < 16; ++i)
        *(float4*)&qr[i * 4] = *(const float4*)(q + off + i * 4);

    float zd = EPS;
    #pragma unroll
    for (int d = 0; d < 64; ++d) zd = fmaf(qr[d], kms[d], zd);
    const float z = 1.0f / zd;

    float* yp = y + off;
    #pragma unroll
    for (int e0 = 0; e0 < 64; e0 += 8) {
        float s0 = 0.f, s1 = 0.f, s2 = 0.f, s3 = 0.f;
        float s4 = 0.f, s5 = 0.f, s6 = 0.f, s7 = 0.f;
        #pragma unroll
        for (int d = 0; d < 64; ++d) {
            const float4 k0 = *(const float4*)&kvs[d][e0];
            const float4 k1 = *(const float4*)&kvs[d][e0 + 4];
            const float qd = qr[d];
            s0 = fmaf(qd, k0.x, s0); s1 = fmaf(qd, k0.y, s1);
            s2 = fmaf(qd, k0.z, s2); s3 = fmaf(qd, k0.w, s3);
            s4 = fmaf(qd, k1.x, s4); s5 = fmaf(qd, k1.y, s5);
            s6 = fmaf(qd, k1.z, s6); s7 = fmaf(qd, k1.w, s7);
        }
        float4 o0 = {s0 * z, s1 * z, s2 * z, s3 * z};
        float4 o1 = {s4 * z, s5 * z, s6 * z, s7 * z};
        *(float4*)(yp + e0) = o0;
        *(float4*)(yp + e0 + 4) = o1;
    }
}

// ---------------------------------------------------------------------------
// depthwise 5x5 SAME conv; out = y(att) + conv, written as bf16 hi/lo split
// directly into Ahi/Alo for the final GEMM.
// ---------------------------------------------------------------------------
__global__ __launch_bounds__(256)
void conv_kernel(const float* __restrict__ v, const float* __restrict__ w,
                 const float* __restrict__ wb, const float* __restrict__ yatt,
                 __nv_bfloat16* __restrict__ Ahi, __nv_bfloat16* __restrict__ Alo)
{
    const int e  = threadIdx.x & 63;
    const int xg = threadIdx.x >> 6;
    const int x  = blockIdx.x * 4 + xg;
    const int y0 = blockIdx.y * 8;
    const int bh = blockIdx.z;
    const int b = bh >> 4, h = bh & 15;

    float wgt[25];
    #pragma unroll
    for (int i = 0; i < 25; ++i) wgt[i] = w[e * 25 + i];
    const float bias = wb[e];

    const size_t cofs = (size_t)b * 4096 * 1024 + h * 64 + e;
    const float* vb = v + cofs;
    const float* yb = yatt + cofs;
    __nv_bfloat16* hb = Ahi + cofs;
    __nv_bfloat16* lb = Alo + cofs;

    float win[5][5];
    #pragma unroll
    for (int r = 0; r < 4; ++r) {
        const int yy = y0 - 2 + r;
        #pragma unroll
        for (int c = 0; c < 5; ++c) {
            const int xx = x - 2 + c;
            win[r][c] = (yy >= 0 && yy < 64 && xx >= 0 && xx < 64)
                        ? vb[(size_t)(yy * 64 + xx) * 1024] : 0.f;
        }
    }

    #pragma unroll
    for (int oy = 0; oy < 8; ++oy) {
        const int yy = y0 + oy + 2;
        #pragma unroll
        for (int c = 0; c < 5; ++c) {
            const int xx = x - 2 + c;
            win[4][c] = (yy < 64 && xx >= 0 && xx < 64)
                        ? vb[(size_t)(yy * 64 + xx) * 1024] : 0.f;
        }
        float acc = bias;
        #pragma unroll
        for (int r = 0; r < 5; ++r)
            #pragma unroll
            for (int c = 0; c < 5; ++c)
                acc = fmaf(win[r][c], wgt[r * 5 + c], acc);

        const size_t po = (size_t)((y0 + oy) * 64 + x) * 1024;
        const float t = yb[po] + acc;
        const __nv_bfloat16 hi = __float2bfloat16(t);
        hb[po] = hi;
        lb[po] = __float2bfloat16(t - __bfloat162float(hi));

        #pragma unroll
        for (int r = 0; r < 4; ++r)
            #pragma unroll
            for (int c = 0; c < 5; ++c) win[r][c] = win[r + 1][c];
    }
}

// ---------------------------------------------------------------------------
extern "C" void kernel_launch(void* const* d_in, const int* in_sizes, int n_in,
                              void* d_out, int out_size)
{
    const float* x     = (const float*)d_in[0];
    const float* Wq    = (const float*)d_in[1];
    const float* Wkv   = (const float*)d_in[2];
    const float* Wproj = (const float*)d_in[3];
    const float* bproj = (const float*)d_in[4];
    const float* dwc_w = (const float*)d_in[5];
    const float* dwc_b = (const float*)d_in[6];
    float* out = (float*)d_out;

    float *q, *k, *v, *y, *km, *kv;
    __nv_bfloat16 *ahi, *alo, *whi, *wlo;
    cudaGetSymbolAddress((void**)&q,   g_q);
    cudaGetSymbolAddress((void**)&k,   g_k);
    cudaGetSymbolAddress((void**)&v,   g_v);
    cudaGetSymbolAddress((void**)&y,   g_y);
    cudaGetSymbolAddress((void**)&km,  g_kmean);
    cudaGetSymbolAddress((void**)&kv,  g_kv);
    cudaGetSymbolAddress((void**)&ahi, g_ahi);
    cudaGetSymbolAddress((void**)&alo, g_alo);
    cudaGetSymbolAddress((void**)&whi, g_whi);
    cudaGetSymbolAddress((void**)&wlo, g_wlo);

    cudaFuncSetAttribute(mma_gemm, cudaFuncAttributeMaxDynamicSharedMemorySize,
                         NSTAGE * STG);

    cudaMemsetAsync(km, 0, 4096 * sizeof(float));
    cudaMemsetAsync(kv, 0, 262144 * sizeof(float));

    // split x; transpose+split weights (combined layout: Wq|Wkv|Wproj)
    asplit<<<16384, 256>>>((const float4*)x, (__nv_bfloat162*)ahi,
                           (__nv_bfloat162*)alo, 4194304);
    wtsplit<<<dim3(32, 32), dim3(32, 8)>>>(Wq,    whi,           wlo,           1024, 1024);
    wtsplit<<<dim3(64, 32), dim3(32, 8)>>>(Wkv,   whi + 1048576, wlo + 1048576, 1024, 2048);
    wtsplit<<<dim3(32, 32), dim3(32, 8)>>>(Wproj, whi + 3145728, wlo + 3145728, 1024, 1024);

    const size_t smem = NSTAGE * STG;
    // merged q/k/v GEMM: N=3072
    mma_gemm<<<dim3(24, 64), 512, smem>>>(ahi, alo, whi, wlo, q, k, v,
                                          nullptr, 0);

    kvmat_kernel<<<dim3(16, 16, 4), 256>>>(k, v, kv, km);
    att_kernel<<<dim3(32, 16, 4), 128>>>(q, kv, km, y);
    // conv: out = y + conv(v), written directly as bf16 hi/lo into ahi/alo
    conv_kernel<<<dim3(16, 8, 64), 256>>>(v, dwc_w, dwc_b, y, ahi, alo);

    // out = (att+conv) @ Wproj + bproj
    mma_gemm<<<dim3(8, 64), 512, smem>>>(ahi, alo, whi + 3145728,
                                         wlo + 3145728, out, nullptr, nullptr,
                                         bproj, 1);
}

// round 5
// speedup vs baseline: 2.0323x; 2.0323x over previous
#include <cuda_runtime.h>
#include <cuda_fp16.h>
#include <cstdint>

#define EPS 1e-6f

// ---------------- scratch (__device__ globals; no allocations allowed) -----
__device__ float g_q[16777216];      // (16384,1024) fp32
__device__ float g_k[16777216];
__device__ float g_v[16777216];
__device__ float g_y[16777216];      // att (fp32)
__device__ float g_kmean[4096];      // (B,1024)
__device__ float g_kv[262144];       // (B,h,64,64)
__device__ float g_kvp[16777216];    // kv partials: [16 nc][B][h][64][64]
__device__ float g_kmp[65536];       // kmean partials: [16 nc][B][1024]
__device__ __half g_a16[16777216];   // A operand fp16 (x, then att+conv)
__device__ __half g_w16[4194304];    // transposed weights fp16 [WqT|WkvT|WprojT]

// ---------------- PTX helpers (baseline sm_80+ features only) --------------
__device__ __forceinline__ uint32_t smem_u32(const void* p) {
    uint32_t a;
    asm("{ .reg .u64 t; cvta.to.shared.u64 t, %1; cvt.u32.u64 %0, t; }"
        : "=r"(a) : "l"(p));
    return a;
}
__device__ __forceinline__ void cpa16(uint32_t s, const void* g) {
    asm volatile("cp.async.cg.shared.global [%0], [%1], 16;" :: "r"(s), "l"(g));
}
__device__ __forceinline__ void ldmx4(uint32_t* r, uint32_t a) {
    asm volatile("ldmatrix.sync.aligned.m8n8.x4.shared.b16 {%0,%1,%2,%3}, [%4];"
                 : "=r"(r[0]), "=r"(r[1]), "=r"(r[2]), "=r"(r[3]) : "r"(a));
}
__device__ __forceinline__ void mma16816(float* c, const uint32_t* a,
                                         uint32_t b0, uint32_t b1) {
    asm volatile(
        "mma.sync.aligned.m16n8k16.row.col.f32.f16.f16.f32 "
        "{%0,%1,%2,%3},{%4,%5,%6,%7},{%8,%9},{%0,%1,%2,%3};"
        : "+f"(c[0]), "+f"(c[1]), "+f"(c[2]), "+f"(c[3])
        : "r"(a[0]), "r"(a[1]), "r"(a[2]), "r"(a[3]), "r"(b0), "r"(b1));
}
#define SWZ64(o) ((o) ^ (((o) >> 3) & 0x30))

// ---------------------------------------------------------------------------
// fp16 single-pass GEMM via mma.sync: D(fp32) = A * B^T
// A: [M,1024] fp16 row-major. B: [N,1024] fp16 row-major (transposed weights).
// CTA tile 128x128, BK=32, 256 threads (8 warps: 2m x 4n, warp tile 64x32),
// 4-stage cp.async ring.
// epi 0: qkv split — group g = (bn*128)>>10: 0->Oq relu+eps, 1->Ok relu+eps,
//        2->Ov raw (cols mod 1024). epi 1: +bias -> Oq. Output ld = 1024.
// ---------------------------------------------------------------------------
#define BK 32
#define TSTG 8192                 // 128 rows x 64B (fp16)
#define STG (2 * TSTG)            // A|B per stage = 16KB
#define NSTAGE 4

__global__ __launch_bounds__(256, 2)
void mma_gemm(const __half* __restrict__ A, const __half* __restrict__ B,
              float* __restrict__ Oq, float* __restrict__ Ok,
              float* __restrict__ Ov, const float* __restrict__ bias, int epi)
{
    extern __shared__ __align__(1024) char smraw[];
    const uint32_t sb = smem_u32(smraw);

    const int tid = threadIdx.x;
    const int wid = tid >> 5, lid = tid & 31;
    const int bm = blockIdx.y, bn = blockIdx.x;

    const int wm = (wid & 1) * 64;    // 2 warps along m
    const int wn = (wid >> 1) * 32;   // 4 warps along n
    const int lr = lid & 15, lc = lid >> 4;

    float acc[4][4][4];
    #pragma unroll
    for (int i = 0; i < 4; ++i)
        #pragma unroll
        for (int j = 0; j < 4; ++j)
            #pragma unroll
            for (int r = 0; r < 4; ++r) acc[i][j][r] = 0.f;

    auto load_stage = [&](int kc, int st) {
        const uint32_t base = sb + st * STG;
        const int kofs = kc * BK;
        #pragma unroll
        for (int i = 0; i < 2; ++i) {
            const int idx = i * 256 + tid;
            const int r = idx >> 2, c = idx & 3;
            const uint32_t so = SWZ64(r * 64 + c * 16);
            cpa16(base + so,        A + (size_t)(bm * 128 + r) * 1024 + kofs + c * 8);
            cpa16(base + TSTG + so, B + (size_t)(bn * 128 + r) * 1024 + kofs + c * 8);
        }
        asm volatile("cp.async.commit_group;" ::: "memory");
    };

    auto compute = [&](int st) {
        const uint32_t base = sb + st * STG;
        #pragma unroll
        for (int ks = 0; ks < 2; ++ks) {
            uint32_t af[4][4], bf[2][4];
            #pragma unroll
            for (int mi = 0; mi < 4; ++mi)
                ldmx4(af[mi], base + SWZ64((wm + mi * 16 + lr) * 64 +
                                           (ks * 2 + lc) * 16));
            #pragma unroll
            for (int nj = 0; nj < 2; ++nj)
                ldmx4(bf[nj], base + TSTG + SWZ64((wn + nj * 16 + lr) * 64 +
                                                  (ks * 2 + lc) * 16));
            #pragma unroll
            for (int mi = 0; mi < 4; ++mi)
                #pragma unroll
                for (int ni = 0; ni < 4; ++ni) {
                    const int nj = ni >> 1, s = ni & 1;
                    mma16816(acc[mi][ni], af[mi], bf[nj][s], bf[nj][s + 2]);
                }
        }
    };

    load_stage(0, 0);
    load_stage(1, 1);
    load_stage(2, 2);

    const int NK = 1024 / BK;   // 32
    for (int kc = 0; kc < NK; ++kc) {
        if (kc < NK - 2)
            asm volatile("cp.async.wait_group 2;" ::: "memory");
        else if (kc == NK - 2)
            asm volatile("cp.async.wait_group 1;" ::: "memory");
        else
            asm volatile("cp.async.wait_group 0;" ::: "memory");
        __syncthreads();
        if (kc + 3 < NK) load_stage(kc + 3, (kc + 3) & (NSTAGE - 1));
        compute(kc & (NSTAGE - 1));
        __syncthreads();
    }

    // ---------------- epilogue ----------------
    const int qrow = lid >> 2;
    const int qcol = (lid & 3) * 2;
    const int g = (bn * 128) >> 10;    // whole CTA in one column group
    float* Obase = (epi == 1) ? Oq : (g == 0 ? Oq : (g == 1 ? Ok : Ov));
    const bool do_relu = (epi == 0) && (g < 2);
    const int ncol0 = (epi == 1) ? bn * 128 : (bn * 128) & 1023;

    #pragma unroll
    for (int mi = 0; mi < 4; ++mi) {
        #pragma unroll
        for (int ni = 0; ni < 4; ++ni) {
            const int cn = ncol0 + wn + ni * 8 + qcol;
            #pragma unroll
            for (int half = 0; half < 2; ++half) {
                const int gm = bm * 128 + wm + mi * 16 + qrow + half * 8;
                float v0 = acc[mi][ni][half * 2 + 0];
                float v1 = acc[mi][ni][half * 2 + 1];
                if (epi == 1) {
                    const float2 bb = *(const float2*)(bias + cn);
                    v0 += bb.x; v1 += bb.y;
                } else if (do_relu) {
                    v0 = fmaxf(v0, 0.f) + EPS;
                    v1 = fmaxf(v1, 0.f) + EPS;
                }
                *(float2*)(Obase + (size_t)gm * 1024 + cn) = make_float2(v0, v1);
            }
        }
    }
}

// ---------------------------------------------------------------------------
// fp32 -> fp16 convert (vectorized by 4)
// ---------------------------------------------------------------------------
__global__ void acvt(const float4* __restrict__ X, __half2* __restrict__ H, int n4)
{
    int i = blockIdx.x * 256 + threadIdx.x;
    if (i >= n4) return;
    float4 v = X[i];
    H[2 * i]     = __floats2half2_rn(v.x, v.y);
    H[2 * i + 1] = __floats2half2_rn(v.z, v.w);
}

// ---------------------------------------------------------------------------
// transpose + fp16 convert of weight W[K,N] -> T[N,K]
// ---------------------------------------------------------------------------
__global__ void wtcvt(const float* __restrict__ W, __half* __restrict__ T,
                      int K, int N)
{
    __shared__ float t[32][33];
    const int n0 = blockIdx.x * 32, k0 = blockIdx.y * 32;
    const int tx = threadIdx.x, ty = threadIdx.y;
    #pragma unroll
    for (int i = 0; i < 32; i += 8)
        t[ty + i][tx] = W[(size_t)(k0 + ty + i) * N + n0 + tx];
    __syncthreads();
    #pragma unroll
    for (int i = 0; i < 32; i += 8)
        T[(size_t)(n0 + ty + i) * K + k0 + tx] = __float2half_rn(t[tx][ty + i]);
}

// ---------------------------------------------------------------------------
// kv partials + kmean partials (no atomics):
// kvp[nc][b][h][d][e] = sum over its 256-row chunk of k[.,d]*v[.,e]
// kmp[nc][b][h*64+d]  = sum over chunk of k[.,d]
// ---------------------------------------------------------------------------
__global__ __launch_bounds__(256)
void kvmat_kernel(const float* __restrict__ k, const float* __restrict__ v,
                  float* __restrict__ kvp, float* __restrict__ kmp)
{
    __shared__ float Ks[32][64];
    __shared__ float Vs[32][64];
    __shared__ float sks[4][64];
    const int tid = threadIdx.x;
    const int nc = blockIdx.x, h = blockIdx.y, b = blockIdx.z;
    const int lr = tid >> 4;
    const int lc = (tid & 15) << 2;
    const int tr = (tid >> 4) << 2;
    const int tc = (tid & 15) << 2;
    const int sd = tid & 63;
    const int sg = tid >> 6;

    float acc[4][4];
    #pragma unroll
    for (int i = 0; i < 4; ++i)
        #pragma unroll
        for (int j = 0; j < 4; ++j) acc[i][j] = 0.f;
    float ks_acc = 0.f;

    const size_t base = ((size_t)(b * 4096 + nc * 256)) * 1024 + h * 64;
    for (int t = 0; t < 256; t += 32) {
        const float* kp = k + base + (size_t)(t + lr) * 1024 + lc;
        const float* vp = v + base + (size_t)(t + lr) * 1024 + lc;
        *(float4*)&Ks[lr][lc]      = *(const float4*)kp;
        *(float4*)&Ks[lr + 16][lc] = *(const float4*)(kp + (size_t)16 * 1024);
        *(float4*)&Vs[lr][lc]      = *(const float4*)vp;
        *(float4*)&Vs[lr + 16][lc] = *(const float4*)(vp + (size_t)16 * 1024);
        __syncthreads();
        #pragma unroll
        for (int nn = 0; nn < 32; ++nn) {
            float a[4], bb[4];
            *(float4*)a  = *(const float4*)&Ks[nn][tr];
            *(float4*)bb = *(const float4*)&Vs[nn][tc];
            #pragma unroll
            for (int i = 0; i < 4; ++i)
                #pragma unroll
                for (int j = 0; j < 4; ++j)
                    acc[i][j] = fmaf(a[i], bb[j], acc[i][j]);
        }
        #pragma unroll
        for (int rr = 0; rr < 8; ++rr)
            ks_acc += Ks[sg * 8 + rr][sd];
        __syncthreads();
    }
    sks[sg][sd] = ks_acc;

    float* kvo = kvp + (((size_t)(nc * 4 + b)) * 16 + h) * 4096;
    #pragma unroll
    for (int i = 0; i < 4; ++i) {
        float4 o = make_float4(acc[i][0], acc[i][1], acc[i][2], acc[i][3]);
        *(float4*)(kvo + (tr + i) * 64 + tc) = o;
    }
    __syncthreads();
    if (tid < 64)
        kmp[(size_t)(nc * 4 + b) * 1024 + h * 64 + tid] =
            sks[0][tid] + sks[1][tid] + sks[2][tid] + sks[3][tid];
}

// ---------------------------------------------------------------------------
// reduce 16 partial slices -> kv (scaled 1/4096) and kmean
// ---------------------------------------------------------------------------
__global__ void reduce_kernel(const float* __restrict__ kvp,
                              const float* __restrict__ kmp,
                              float* __restrict__ kv, float* __restrict__ km)
{
    const int i = blockIdx.x * 256 + threadIdx.x;
    if (i < 262144) {
        float s = 0.f;
        #pragma unroll
        for (int nc = 0; nc < 16; ++nc) s += kvp[(size_t)nc * 262144 + i];
        kv[i] = s * (1.0f / 4096.0f);
    } else if (i < 262144 + 4096) {
        const int j = i - 262144;
        float s = 0.f;
        #pragma unroll
        for (int nc = 0; nc < 16; ++nc) s += kmp[nc * 4096 + j];
        km[j] = s * (1.0f / 4096.0f);
    }
}

// ---------------------------------------------------------------------------
// att -> y (writes '=')
// ---------------------------------------------------------------------------
__global__ __launch_bounds__(128)
void att_kernel(const float* __restrict__ q, const float* __restrict__ kvm,
                const float* __restrict__ km, float* __restrict__ y)
{
    __shared__ float kvs[64][64];
    __shared__ float kms[64];
    const int b = blockIdx.z, h = blockIdx.y;
    const int n = blockIdx.x * 128 + threadIdx.x;

    const float* kvp = kvm + (size_t)(b * 16 + h) * 4096;
    for (int i = threadIdx.x; i < 1024; i += 128)
        ((float4*)kvs)[i] = ((const float4*)kvp)[i];
    if (threadIdx.x < 16)
        ((float4*)kms)[threadIdx.x] =
            ((const float4*)(km + b * 1024 + h * 64))[threadIdx.x];
    __syncthreads();

    const size_t off = ((size_t)(b * 4096 + n)) * 1024 + h * 64;
    float qr[64];
    #pragma unroll
    for (int i = 0; i < 16; ++i)
        *(float4*)&qr[i * 4] = *(const float4*)(q + off + i * 4);

    float zd = EPS;
    #pragma unroll
    for (int d = 0; d < 64; ++d) zd = fmaf(qr[d], kms[d], zd);
    const float z = 1.0f / zd;

    float* yp = y + off;
    #pragma unroll
    for (int e0 = 0; e0 < 64; e0 += 8) {
        float s0 = 0.f, s1 = 0.f, s2 = 0.f, s3 = 0.f;
        float s4 = 0.f, s5 = 0.f, s6 = 0.f, s7 = 0.f;
        #pragma unroll
        for (int d = 0; d < 64; ++d) {
            const float4 k0 = *(const float4*)&kvs[d][e0];
            const float4 k1 = *(const float4*)&kvs[d][e0 + 4];
            const float qd = qr[d];
            s0 = fmaf(qd, k0.x, s0); s1 = fmaf(qd, k0.y, s1);
            s2 = fmaf(qd, k0.z, s2); s3 = fmaf(qd, k0.w, s3);
            s4 = fmaf(qd, k1.x, s4); s5 = fmaf(qd, k1.y, s5);
            s6 = fmaf(qd, k1.z, s6); s7 = fmaf(qd, k1.w, s7);
        }
        float4 o0 = {s0 * z, s1 * z, s2 * z, s3 * z};
        float4 o1 = {s4 * z, s5 * z, s6 * z, s7 * z};
        *(float4*)(yp + e0) = o0;
        *(float4*)(yp + e0 + 4) = o1;
    }
}

// ---------------------------------------------------------------------------
// depthwise 5x5 SAME conv; out = y(att) + conv, written as fp16 into A16
// for the final GEMM.
// ---------------------------------------------------------------------------
__global__ __launch_bounds__(256)
void conv_kernel(const float* __restrict__ v, const float* __restrict__ w,
                 const float* __restrict__ wb, const float* __restrict__ yatt,
                 __half* __restrict__ A16)
{
    const int e  = threadIdx.x & 63;
    const int xg = threadIdx.x >> 6;
    const int x  = blockIdx.x * 4 + xg;
    const int y0 = blockIdx.y * 8;
    const int bh = blockIdx.z;
    const int b = bh >> 4, h = bh & 15;

    float wgt[25];
    #pragma unroll
    for (int i = 0; i < 25; ++i) wgt[i] = w[e * 25 + i];
    const float bias = wb[e];

    const size_t cofs = (size_t)b * 4096 * 1024 + h * 64 + e;
    const float* vb = v + cofs;
    const float* yb = yatt + cofs;
    __half* ab = A16 + cofs;

    float win[5][5];
    #pragma unroll
    for (int r = 0; r < 4; ++r) {
        const int yy = y0 - 2 + r;
        #pragma unroll
        for (int c = 0; c < 5; ++c) {
            const int xx = x - 2 + c;
            win[r][c] = (yy >= 0 && yy < 64 && xx >= 0 && xx < 64)
                        ? vb[(size_t)(yy * 64 + xx) * 1024] : 0.f;
        }
    }

    #pragma unroll
    for (int oy = 0; oy < 8; ++oy) {
        const int yy = y0 + oy + 2;
        #pragma unroll
        for (int c = 0; c < 5; ++c) {
            const int xx = x - 2 + c;
            win[4][c] = (yy < 64 && xx >= 0 && xx < 64)
                        ? vb[(size_t)(yy * 64 + xx) * 1024] : 0.f;
        }
        float acc = bias;
        #pragma unroll
        for (int r = 0; r < 5; ++r)
            #pragma unroll
            for (int c = 0; c < 5; ++c)
                acc = fmaf(win[r][c], wgt[r * 5 + c], acc);

        const size_t po = (size_t)((y0 + oy) * 64 + x) * 1024;
        ab[po] = __float2half_rn(yb[po] + acc);

        #pragma unroll
        for (int r = 0; r < 4; ++r)
            #pragma unroll
            for (int c = 0; c < 5; ++c) win[r][c] = win[r + 1][c];
    }
}

// ---------------------------------------------------------------------------
extern "C" void kernel_launch(void* const* d_in, const int* in_sizes, int n_in,
                              void* d_out, int out_size)
{
    const float* x     = (const float*)d_in[0];
    const float* Wq    = (const float*)d_in[1];
    const float* Wkv   = (const float*)d_in[2];
    const float* Wproj = (const float*)d_in[3];
    const float* bproj = (const float*)d_in[4];
    const float* dwc_w = (const float*)d_in[5];
    const float* dwc_b = (const float*)d_in[6];
    float* out = (float*)d_out;

    float *q, *k, *v, *y, *km, *kv, *kvp, *kmp;
    __half *a16, *w16;
    cudaGetSymbolAddress((void**)&q,   g_q);
    cudaGetSymbolAddress((void**)&k,   g_k);
    cudaGetSymbolAddress((void**)&v,   g_v);
    cudaGetSymbolAddress((void**)&y,   g_y);
    cudaGetSymbolAddress((void**)&km,  g_kmean);
    cudaGetSymbolAddress((void**)&kv,  g_kv);
    cudaGetSymbolAddress((void**)&kvp, g_kvp);
    cudaGetSymbolAddress((void**)&kmp, g_kmp);
    cudaGetSymbolAddress((void**)&a16, g_a16);
    cudaGetSymbolAddress((void**)&w16, g_w16);

    cudaFuncSetAttribute(mma_gemm, cudaFuncAttributeMaxDynamicSharedMemorySize,
                         NSTAGE * STG);

    // launches 1-5 (so the 6th = big GEMM gets the ncu -s 5 -c 1 capture)
    acvt<<<8192, 256>>>((const float4*)x, (__half2*)a16, 2097152);
    acvt<<<8192, 256>>>((const float4*)x + 2097152,
                        (__half2*)a16 + 4194304, 2097152);
    wtcvt<<<dim3(32, 32), dim3(32, 8)>>>(Wq,    w16,           1024, 1024);
    wtcvt<<<dim3(64, 32), dim3(32, 8)>>>(Wkv,   w16 + 1048576, 1024, 2048);
    wtcvt<<<dim3(32, 32), dim3(32, 8)>>>(Wproj, w16 + 3145728, 1024, 1024);

    const size_t smem = NSTAGE * STG;
    // merged q/k/v GEMM: N=3072 (rows: 0-1023 q, 1024-2047 k, 2048-3071 v)
    mma_gemm<<<dim3(24, 128), 256, smem>>>(a16, w16, q, k, v, nullptr, 0);

    kvmat_kernel<<<dim3(16, 16, 4), 256>>>(k, v, kvp, kmp);
    reduce_kernel<<<1040, 256>>>(kvp, kmp, kv, km);
    att_kernel<<<dim3(32, 16, 4), 128>>>(q, kv, km, y);
    // conv: att + conv(v), written directly as fp16 into a16
    conv_kernel<<<dim3(16, 8, 64), 256>>>(v, dwc_w, dwc_b, y, a16);

    // out = (att+conv) @ Wproj + bproj
    mma_gemm<<<dim3(8, 128), 256, smem>>>(a16, w16 + 3145728, out, nullptr,
                                          nullptr, bproj, 1);
}

// round 6
// speedup vs baseline: 2.2277x; 1.0961x over previous
#include <cuda_runtime.h>
#include <cuda_fp16.h>
#include <cstdint>

#define EPS 1e-6f

// ---------------- scratch (__device__ globals; no allocations allowed) -----
__device__ __half g_q16[16777216];   // (16384,1024) fp16
__device__ __half g_k16[16777216];
__device__ __half g_v16[16777216];
__device__ float g_kmean[4096];      // (B,1024)
__device__ float g_kv[262144];       // (B,h,64,64)
__device__ float g_kvp[16777216];    // kv partials: [16 nc][B][h][64][64]
__device__ float g_kmp[65536];       // kmean partials: [16 nc][B][1024]
__device__ __half g_a16[16777216];   // A operand fp16 (x, then att+conv)
__device__ __half g_w16[4194304];    // transposed weights fp16 [WqT|WkvT|WprojT]

// ---------------- PTX helpers (baseline sm_80+ features only) --------------
__device__ __forceinline__ uint32_t smem_u32(const void* p) {
    uint32_t a;
    asm("{ .reg .u64 t; cvta.to.shared.u64 t, %1; cvt.u32.u64 %0, t; }"
        : "=r"(a) : "l"(p));
    return a;
}
__device__ __forceinline__ void cpa16(uint32_t s, const void* g) {
    asm volatile("cp.async.cg.shared.global [%0], [%1], 16;" :: "r"(s), "l"(g));
}
__device__ __forceinline__ void ldmx4(uint32_t* r, uint32_t a) {
    asm volatile("ldmatrix.sync.aligned.m8n8.x4.shared.b16 {%0,%1,%2,%3}, [%4];"
                 : "=r"(r[0]), "=r"(r[1]), "=r"(r[2]), "=r"(r[3]) : "r"(a));
}
__device__ __forceinline__ void mma16816(float* c, const uint32_t* a,
                                         uint32_t b0, uint32_t b1) {
    asm volatile(
        "mma.sync.aligned.m16n8k16.row.col.f32.f16.f16.f32 "
        "{%0,%1,%2,%3},{%4,%5,%6,%7},{%8,%9},{%0,%1,%2,%3};"
        : "+f"(c[0]), "+f"(c[1]), "+f"(c[2]), "+f"(c[3])
        : "r"(a[0]), "r"(a[1]), "r"(a[2]), "r"(a[3]), "r"(b0), "r"(b1));
}
#define SWZ128(o) ((o) ^ (((o) >> 3) & 0x70))

// ---------------------------------------------------------------------------
// fp16 single-pass GEMM via mma.sync: D(fp32 acc) = A * B^T
// A: [M,1024] fp16 row-major. B: [N,1024] fp16 row-major (transposed weights).
// CTA tile 128x128, BK=64 (128B rows, SW128), 256 threads (8 warps: 2m x 4n,
// warp tile 64x32), 3-stage cp.async ring, ONE __syncthreads per K-chunk.
// epi 0: qkv split -> fp16 outputs (group g: 0 relu->Oq, 1 relu->Ok, 2 raw->Ov)
// epi 1: +bias -> fp32 Oq. Output ld = 1024.
// ---------------------------------------------------------------------------
#define BK 64
#define TSTG 16384                // 128 rows x 128B
#define STG (2 * TSTG)            // A|B per stage = 32KB
#define NSTAGE 3

__global__ __launch_bounds__(256, 2)
void mma_gemm(const __half* __restrict__ A, const __half* __restrict__ B,
              void* __restrict__ Oq, void* __restrict__ Ok,
              void* __restrict__ Ov, const float* __restrict__ bias, int epi)
{
    extern __shared__ __align__(1024) char smraw[];
    const uint32_t sb = smem_u32(smraw);

    const int tid = threadIdx.x;
    const int wid = tid >> 5, lid = tid & 31;
    const int bm = blockIdx.y, bn = blockIdx.x;

    const int wm = (wid & 1) * 64;    // 2 warps along m
    const int wn = (wid >> 1) * 32;   // 4 warps along n
    const int lr = lid & 15, lc = lid >> 4;

    float acc[4][4][4];
    #pragma unroll
    for (int i = 0; i < 4; ++i)
        #pragma unroll
        for (int j = 0; j < 4; ++j)
            #pragma unroll
            for (int r = 0; r < 4; ++r) acc[i][j][r] = 0.f;

    // per stage: A,B each 128 rows x 128B = 1024 x 16B chunks; 4 per thread
    auto load_stage = [&](int kc, int st) {
        const uint32_t base = sb + st * STG;
        const int kofs = kc * BK;
        #pragma unroll
        for (int i = 0; i < 4; ++i) {
            const int idx = i * 256 + tid;
            const int r = idx >> 3, c = idx & 7;
            const uint32_t so = SWZ128(r * 128 + c * 16);
            cpa16(base + so,        A + (size_t)(bm * 128 + r) * 1024 + kofs + c * 8);
            cpa16(base + TSTG + so, B + (size_t)(bn * 128 + r) * 1024 + kofs + c * 8);
        }
        asm volatile("cp.async.commit_group;" ::: "memory");
    };

    auto compute = [&](int st) {
        const uint32_t base = sb + st * STG;
        #pragma unroll
        for (int ks = 0; ks < 4; ++ks) {
            uint32_t af[4][4], bf[2][4];
            #pragma unroll
            for (int mi = 0; mi < 4; ++mi)
                ldmx4(af[mi], base + SWZ128((wm + mi * 16 + lr) * 128 +
                                            ks * 32 + lc * 16));
            #pragma unroll
            for (int nj = 0; nj < 2; ++nj)
                ldmx4(bf[nj], base + TSTG + SWZ128((wn + nj * 16 + lr) * 128 +
                                                   ks * 32 + lc * 16));
            #pragma unroll
            for (int mi = 0; mi < 4; ++mi)
                #pragma unroll
                for (int ni = 0; ni < 4; ++ni) {
                    const int nj = ni >> 1, s = ni & 1;
                    mma16816(acc[mi][ni], af[mi], bf[nj][s], bf[nj][s + 2]);
                }
        }
    };

    load_stage(0, 0);
    load_stage(1, 1);

    const int NK = 1024 / BK;   // 16
    int st = 0;
    for (int kc = 0; kc < NK; ++kc) {
        if (kc < NK - 1)
            asm volatile("cp.async.wait_group 1;" ::: "memory");
        else
            asm volatile("cp.async.wait_group 0;" ::: "memory");
        __syncthreads();
        if (kc + 2 < NK) load_stage(kc + 2, (st + 2) % NSTAGE);
        compute(st);
        st = (st + 1) % NSTAGE;
    }

    // ---------------- epilogue ----------------
    const int qrow = lid >> 2;
    const int qcol = (lid & 3) * 2;
    const int g = (bn * 128) >> 10;    // whole CTA in one 1024-col group
    const int ncol0 = (epi == 1) ? bn * 128 : (bn * 128) & 1023;

    if (epi == 0) {
        __half* Obase = (__half*)(g == 0 ? Oq : (g == 1 ? Ok : Ov));
        const bool do_relu = (g < 2);
        #pragma unroll
        for (int mi = 0; mi < 4; ++mi)
            #pragma unroll
            for (int ni = 0; ni < 4; ++ni) {
                const int cn = ncol0 + wn + ni * 8 + qcol;
                #pragma unroll
                for (int half = 0; half < 2; ++half) {
                    const int gm = bm * 128 + wm + mi * 16 + qrow + half * 8;
                    float v0 = acc[mi][ni][half * 2 + 0];
                    float v1 = acc[mi][ni][half * 2 + 1];
                    if (do_relu) {
                        v0 = fmaxf(v0, 0.f) + EPS;
                        v1 = fmaxf(v1, 0.f) + EPS;
                    }
                    *(__half2*)(Obase + (size_t)gm * 1024 + cn) =
                        __floats2half2_rn(v0, v1);
                }
            }
    } else {
        float* Obase = (float*)Oq;
        #pragma unroll
        for (int mi = 0; mi < 4; ++mi)
            #pragma unroll
            for (int ni = 0; ni < 4; ++ni) {
                const int cn = ncol0 + wn + ni * 8 + qcol;
                #pragma unroll
                for (int half = 0; half < 2; ++half) {
                    const int gm = bm * 128 + wm + mi * 16 + qrow + half * 8;
                    const float2 bb = *(const float2*)(bias + cn);
                    *(float2*)(Obase + (size_t)gm * 1024 + cn) =
                        make_float2(acc[mi][ni][half * 2 + 0] + bb.x,
                                    acc[mi][ni][half * 2 + 1] + bb.y);
                }
            }
    }
}

// ---------------------------------------------------------------------------
// fp32 -> fp16 convert (vectorized by 4)
// ---------------------------------------------------------------------------
__global__ void acvt(const float4* __restrict__ X, __half2* __restrict__ H, int n4)
{
    int i = blockIdx.x * 256 + threadIdx.x;
    if (i >= n4) return;
    float4 v = X[i];
    H[2 * i]     = __floats2half2_rn(v.x, v.y);
    H[2 * i + 1] = __floats2half2_rn(v.z, v.w);
}

// ---------------------------------------------------------------------------
// transpose + fp16 convert of weight W[K,N] -> T[N,K]
// ---------------------------------------------------------------------------
__global__ void wtcvt(const float* __restrict__ W, __half* __restrict__ T,
                      int K, int N)
{
    __shared__ float t[32][33];
    const int n0 = blockIdx.x * 32, k0 = blockIdx.y * 32;
    const int tx = threadIdx.x, ty = threadIdx.y;
    #pragma unroll
    for (int i = 0; i < 32; i += 8)
        t[ty + i][tx] = W[(size_t)(k0 + ty + i) * N + n0 + tx];
    __syncthreads();
    #pragma unroll
    for (int i = 0; i < 32; i += 8)
        T[(size_t)(n0 + ty + i) * K + k0 + tx] = __float2half_rn(t[tx][ty + i]);
}

// ---------------------------------------------------------------------------
// kv partials + kmean partials (fp16 inputs, fp32 accumulation, no atomics)
// ---------------------------------------------------------------------------
__global__ __launch_bounds__(256)
void kvmat_kernel(const __half* __restrict__ k, const __half* __restrict__ v,
                  float* __restrict__ kvp, float* __restrict__ kmp)
{
    __shared__ float Ks[32][64];
    __shared__ float Vs[32][64];
    __shared__ float sks[4][64];
    const int tid = threadIdx.x;
    const int nc = blockIdx.x, h = blockIdx.y, b = blockIdx.z;
    const int lr = tid >> 3;           // 0..31 (row)
    const int lc = (tid & 7) << 3;     // half-offset 0..56
    const int tr = (tid >> 4) << 2;
    const int tc = (tid & 15) << 2;
    const int sd = tid & 63;
    const int sg = tid >> 6;

    float acc[4][4];
    #pragma unroll
    for (int i = 0; i < 4; ++i)
        #pragma unroll
        for (int j = 0; j < 4; ++j) acc[i][j] = 0.f;
    float ks_acc = 0.f;

    const size_t base = ((size_t)(b * 4096 + nc * 256)) * 1024 + h * 64;
    for (int t = 0; t < 256; t += 32) {
        const uint4 kd = *(const uint4*)(k + base + (size_t)(t + lr) * 1024 + lc);
        const uint4 vd = *(const uint4*)(v + base + (size_t)(t + lr) * 1024 + lc);
        const __half2* kh = (const __half2*)&kd;
        const __half2* vh = (const __half2*)&vd;
        #pragma unroll
        for (int j = 0; j < 4; ++j) {
            const float2 kf = __half22float2(kh[j]);
            const float2 vf = __half22float2(vh[j]);
            Ks[lr][lc + 2 * j]     = kf.x;
            Ks[lr][lc + 2 * j + 1] = kf.y;
            Vs[lr][lc + 2 * j]     = vf.x;
            Vs[lr][lc + 2 * j + 1] = vf.y;
        }
        __syncthreads();
        #pragma unroll
        for (int nn = 0; nn < 32; ++nn) {
            float a[4], bb[4];
            *(float4*)a  = *(const float4*)&Ks[nn][tr];
            *(float4*)bb = *(const float4*)&Vs[nn][tc];
            #pragma unroll
            for (int i = 0; i < 4; ++i)
                #pragma unroll
                for (int j = 0; j < 4; ++j)
                    acc[i][j] = fmaf(a[i], bb[j], acc[i][j]);
        }
        #pragma unroll
        for (int rr = 0; rr < 8; ++rr)
            ks_acc += Ks[sg * 8 + rr][sd];
        __syncthreads();
    }
    sks[sg][sd] = ks_acc;

    float* kvo = kvp + (((size_t)(nc * 4 + b)) * 16 + h) * 4096;
    #pragma unroll
    for (int i = 0; i < 4; ++i) {
        float4 o = make_float4(acc[i][0], acc[i][1], acc[i][2], acc[i][3]);
        *(float4*)(kvo + (tr + i) * 64 + tc) = o;
    }
    __syncthreads();
    if (tid < 64)
        kmp[(size_t)(nc * 4 + b) * 1024 + h * 64 + tid] =
            sks[0][tid] + sks[1][tid] + sks[2][tid] + sks[3][tid];
}

// ---------------------------------------------------------------------------
// reduce 16 partial slices -> kv (scaled 1/4096) and kmean
// ---------------------------------------------------------------------------
__global__ void reduce_kernel(const float* __restrict__ kvp,
                              const float* __restrict__ kmp,
                              float* __restrict__ kv, float* __restrict__ km)
{
    const int i = blockIdx.x * 256 + threadIdx.x;
    if (i < 262144) {
        float s = 0.f;
        #pragma unroll
        for (int nc = 0; nc < 16; ++nc) s += kvp[(size_t)nc * 262144 + i];
        kv[i] = s * (1.0f / 4096.0f);
    } else if (i < 262144 + 4096) {
        const int j = i - 262144;
        float s = 0.f;
        #pragma unroll
        for (int nc = 0; nc < 16; ++nc) s += kmp[nc * 4096 + j];
        km[j] = s * (1.0f / 4096.0f);
    }
}

// ---------------------------------------------------------------------------
// att: writes fp16 att into A16 (conv then adds conv term in-place)
// ---------------------------------------------------------------------------
__global__ __launch_bounds__(128)
void att_kernel(const __half* __restrict__ q, const float* __restrict__ kvm,
                const float* __restrict__ km, __half* __restrict__ A16)
{
    __shared__ float kvs[64][64];
    __shared__ float kms[64];
    const int b = blockIdx.z, h = blockIdx.y;
    const int n = blockIdx.x * 128 + threadIdx.x;

    const float* kvp = kvm + (size_t)(b * 16 + h) * 4096;
    for (int i = threadIdx.x; i < 1024; i += 128)
        ((float4*)kvs)[i] = ((const float4*)kvp)[i];
    if (threadIdx.x < 16)
        ((float4*)kms)[threadIdx.x] =
            ((const float4*)(km + b * 1024 + h * 64))[threadIdx.x];
    __syncthreads();

    const size_t off = ((size_t)(b * 4096 + n)) * 1024 + h * 64;
    float qr[64];
    #pragma unroll
    for (int i = 0; i < 8; ++i) {
        const uint4 qd = *(const uint4*)(q + off + i * 8);
        const __half2* qh = (const __half2*)&qd;
        #pragma unroll
        for (int j = 0; j < 4; ++j) {
            const float2 f = __half22float2(qh[j]);
            qr[i * 8 + 2 * j]     = f.x;
            qr[i * 8 + 2 * j + 1] = f.y;
        }
    }

    float zd = EPS;
    #pragma unroll
    for (int d = 0; d < 64; ++d) zd = fmaf(qr[d], kms[d], zd);
    const float z = 1.0f / zd;

    __half* yp = A16 + off;
    #pragma unroll
    for (int e0 = 0; e0 < 64; e0 += 8) {
        float s0 = 0.f, s1 = 0.f, s2 = 0.f, s3 = 0.f;
        float s4 = 0.f, s5 = 0.f, s6 = 0.f, s7 = 0.f;
        #pragma unroll
        for (int d = 0; d < 64; ++d) {
            const float4 k0 = *(const float4*)&kvs[d][e0];
            const float4 k1 = *(const float4*)&kvs[d][e0 + 4];
            const float qd = qr[d];
            s0 = fmaf(qd, k0.x, s0); s1 = fmaf(qd, k0.y, s1);
            s2 = fmaf(qd, k0.z, s2); s3 = fmaf(qd, k0.w, s3);
            s4 = fmaf(qd, k1.x, s4); s5 = fmaf(qd, k1.y, s5);
            s6 = fmaf(qd, k1.z, s6); s7 = fmaf(qd, k1.w, s7);
        }
        uint2 o;
        ((__half2*)&o)[0] = __floats2half2_rn(s0 * z, s1 * z);
        ((__half2*)&o)[1] = __floats2half2_rn(s2 * z, s3 * z);
        *(uint2*)(yp + e0) = o;
        ((__half2*)&o)[0] = __floats2half2_rn(s4 * z, s5 * z);
        ((__half2*)&o)[1] = __floats2half2_rn(s6 * z, s7 * z);
        *(uint2*)(yp + e0 + 4) = o;
    }
}

// ---------------------------------------------------------------------------
// depthwise 5x5 SAME conv on fp16 v; A16 += conv (fp16 read-modify-write)
// ---------------------------------------------------------------------------
__global__ __launch_bounds__(256)
void conv_kernel(const __half* __restrict__ v, const float* __restrict__ w,
                 const float* __restrict__ wb, __half* __restrict__ A16)
{
    const int e  = threadIdx.x & 63;
    const int xg = threadIdx.x >> 6;
    const int x  = blockIdx.x * 4 + xg;
    const int y0 = blockIdx.y * 8;
    const int bh = blockIdx.z;
    const int b = bh >> 4, h = bh & 15;

    float wgt[25];
    #pragma unroll
    for (int i = 0; i < 25; ++i) wgt[i] = w[e * 25 + i];
    const float bias = wb[e];

    const size_t cofs = (size_t)b * 4096 * 1024 + h * 64 + e;
    const __half* vb = v + cofs;
    __half* ab = A16 + cofs;

    float win[5][5];
    #pragma unroll
    for (int r = 0; r < 4; ++r) {
        const int yy = y0 - 2 + r;
        #pragma unroll
        for (int c = 0; c < 5; ++c) {
            const int xx = x - 2 + c;
            win[r][c] = (yy >= 0 && yy < 64 && xx >= 0 && xx < 64)
                        ? __half2float(vb[(size_t)(yy * 64 + xx) * 1024]) : 0.f;
        }
    }

    #pragma unroll
    for (int oy = 0; oy < 8; ++oy) {
        const int yy = y0 + oy + 2;
        #pragma unroll
        for (int c = 0; c < 5; ++c) {
            const int xx = x - 2 + c;
            win[4][c] = (yy < 64 && xx >= 0 && xx < 64)
                        ? __half2float(vb[(size_t)(yy * 64 + xx) * 1024]) : 0.f;
        }
        float acc = bias;
        #pragma unroll
        for (int r = 0; r < 5; ++r)
            #pragma unroll
            for (int c = 0; c < 5; ++c)
                acc = fmaf(win[r][c], wgt[r * 5 + c], acc);

        const size_t po = (size_t)((y0 + oy) * 64 + x) * 1024;
        ab[po] = __float2half_rn(__half2float(ab[po]) + acc);

        #pragma unroll
        for (int r = 0; r < 4; ++r)
            #pragma unroll
            for (int c = 0; c < 5; ++c) win[r][c] = win[r + 1][c];
    }
}

// ---------------------------------------------------------------------------
extern "C" void kernel_launch(void* const* d_in, const int* in_sizes, int n_in,
                              void* d_out, int out_size)
{
    const float* x     = (const float*)d_in[0];
    const float* Wq    = (const float*)d_in[1];
    const float* Wkv   = (const float*)d_in[2];
    const float* Wproj = (const float*)d_in[3];
    const float* bproj = (const float*)d_in[4];
    const float* dwc_w = (const float*)d_in[5];
    const float* dwc_b = (const float*)d_in[6];
    float* out = (float*)d_out;

    float *km, *kv, *kvp, *kmp;
    __half *q16, *k16, *v16, *a16, *w16;
    cudaGetSymbolAddress((void**)&q16, g_q16);
    cudaGetSymbolAddress((void**)&k16, g_k16);
    cudaGetSymbolAddress((void**)&v16, g_v16);
    cudaGetSymbolAddress((void**)&km,  g_kmean);
    cudaGetSymbolAddress((void**)&kv,  g_kv);
    cudaGetSymbolAddress((void**)&kvp, g_kvp);
    cudaGetSymbolAddress((void**)&kmp, g_kmp);
    cudaGetSymbolAddress((void**)&a16, g_a16);
    cudaGetSymbolAddress((void**)&w16, g_w16);

    cudaFuncSetAttribute(mma_gemm, cudaFuncAttributeMaxDynamicSharedMemorySize,
                         NSTAGE * STG);

    acvt<<<16384, 256>>>((const float4*)x, (__half2*)a16, 4194304);
    wtcvt<<<dim3(32, 32), dim3(32, 8)>>>(Wq,    w16,           1024, 1024);
    wtcvt<<<dim3(64, 32), dim3(32, 8)>>>(Wkv,   w16 + 1048576, 1024, 2048);
    wtcvt<<<dim3(32, 32), dim3(32, 8)>>>(Wproj, w16 + 3145728, 1024, 1024);

    const size_t smem = NSTAGE * STG;
    // merged q/k/v GEMM: N=3072 -> fp16 q,k,v
    mma_gemm<<<dim3(24, 128), 256, smem>>>(a16, w16, q16, k16, v16, nullptr, 0);

    kvmat_kernel<<<dim3(16, 16, 4), 256>>>(k16, v16, kvp, kmp);
    reduce_kernel<<<1040, 256>>>(kvp, kmp, kv, km);
    att_kernel<<<dim3(32, 16, 4), 128>>>(q16, kv, km, a16);
    conv_kernel<<<dim3(16, 8, 64), 256>>>(v16, dwc_w, dwc_b, a16);

    // out = (att+conv) @ Wproj + bproj  (fp32 out)
    mma_gemm<<<dim3(8, 128), 256, smem>>>(a16, w16 + 3145728, out, nullptr,
                                          nullptr, bproj, 1);
}

// round 8
// speedup vs baseline: 2.2852x; 1.0258x over previous
#include <cuda_runtime.h>
#include <cuda_fp16.h>
#include <cstdint>

#define EPS 1e-6f

// ---------------- scratch (__device__ globals; no allocations allowed) -----
__device__ __half g_q16[16777216];   // (16384,1024) fp16
__device__ __half g_k16[16777216];
__device__ __half g_v16[16777216];
__device__ float g_kmean[4096];      // (B,1024)
__device__ __half g_kvt16[262144];   // kv^T fp16: [b,h][e][d]
__device__ float g_kvp[16777216];    // kv partials: [16 nc][B][h][64][64]
__device__ float g_kmp[65536];       // kmean partials: [16 nc][B][1024]
__device__ __half g_a16[16777216];   // A operand fp16 (x, then att+conv)
__device__ __half g_w16[4194304];    // transposed weights fp16 [WqT|WkvT|WprojT]

// ---------------- PTX helpers (baseline sm_80+ features only) --------------
__device__ __forceinline__ uint32_t smem_u32(const void* p) {
    uint32_t a;
    asm("{ .reg .u64 t; cvta.to.shared.u64 t, %1; cvt.u32.u64 %0, t; }"
        : "=r"(a) : "l"(p));
    return a;
}
__device__ __forceinline__ void cpa16(uint32_t s, const void* g) {
    asm volatile("cp.async.cg.shared.global [%0], [%1], 16;" :: "r"(s), "l"(g));
}
__device__ __forceinline__ void ldmx4(uint32_t* r, uint32_t a) {
    asm volatile("ldmatrix.sync.aligned.m8n8.x4.shared.b16 {%0,%1,%2,%3}, [%4];"
                 : "=r"(r[0]), "=r"(r[1]), "=r"(r[2]), "=r"(r[3]) : "r"(a));
}
__device__ __forceinline__ void mma16816(float* c, const uint32_t* a,
                                         uint32_t b0, uint32_t b1) {
    asm volatile(
        "mma.sync.aligned.m16n8k16.row.col.f32.f16.f16.f32 "
        "{%0,%1,%2,%3},{%4,%5,%6,%7},{%8,%9},{%0,%1,%2,%3};"
        : "+f"(c[0]), "+f"(c[1]), "+f"(c[2]), "+f"(c[3])
        : "r"(a[0]), "r"(a[1]), "r"(a[2]), "r"(a[3]), "r"(b0), "r"(b1));
}
#define SWZ128(o) ((o) ^ (((o) >> 3) & 0x70))

// ---------------------------------------------------------------------------
// fp16 single-pass GEMM: D(fp32 acc) = A * B^T
// CTA tile 256x128, BK=64 (128B rows, SW128), 512 threads (16 warps: 4m x 4n,
// warp tile 64x32), 3-stage cp.async ring, one __syncthreads per K-chunk.
// epi 0: qkv split -> fp16 (group g: 0 relu->Oq, 1 relu->Ok, 2 raw->Ov)
// epi 1: +bias -> fp32 Oq. Output ld = 1024.
// ---------------------------------------------------------------------------
#define BK 64
#define A_STG 32768               // 256 rows x 128B
#define B_STG 16384               // 128 rows x 128B
#define STG (A_STG + B_STG)       // 48KB
#define NSTAGE 3

__global__ __launch_bounds__(512, 1)
void mma_gemm(const __half* __restrict__ A, const __half* __restrict__ B,
              void* __restrict__ Oq, void* __restrict__ Ok,
              void* __restrict__ Ov, const float* __restrict__ bias, int epi)
{
    extern __shared__ __align__(1024) char smraw[];
    const uint32_t sb = smem_u32(smraw);

    const int tid = threadIdx.x;
    const int wid = tid >> 5, lid = tid & 31;
    const int bm = blockIdx.y, bn = blockIdx.x;

    const int wm = (wid & 3) * 64;    // 4 warps along m
    const int wn = (wid >> 2) * 32;   // 4 warps along n
    const int lr = lid & 15, lc = lid >> 4;

    float acc[4][4][4];
    #pragma unroll
    for (int i = 0; i < 4; ++i)
        #pragma unroll
        for (int j = 0; j < 4; ++j)
            #pragma unroll
            for (int r = 0; r < 4; ++r) acc[i][j][r] = 0.f;

    auto load_stage = [&](int kc, int st) {
        const uint32_t base = sb + st * STG;
        const int kofs = kc * BK;
        #pragma unroll
        for (int i = 0; i < 4; ++i) {
            const int idx = i * 512 + tid;
            const int r = idx >> 3, c = idx & 7;
            cpa16(base + SWZ128(r * 128 + c * 16),
                  A + (size_t)(bm * 256 + r) * 1024 + kofs + c * 8);
        }
        #pragma unroll
        for (int i = 0; i < 2; ++i) {
            const int idx = i * 512 + tid;
            const int r = idx >> 3, c = idx & 7;
            cpa16(base + A_STG + SWZ128(r * 128 + c * 16),
                  B + (size_t)(bn * 128 + r) * 1024 + kofs + c * 8);
        }
        asm volatile("cp.async.commit_group;" ::: "memory");
    };

    auto compute = [&](int st) {
        const uint32_t base = sb + st * STG;
        #pragma unroll
        for (int ks = 0; ks < 4; ++ks) {
            uint32_t af[4][4], bf[2][4];
            #pragma unroll
            for (int mi = 0; mi < 4; ++mi)
                ldmx4(af[mi], base + SWZ128((wm + mi * 16 + lr) * 128 +
                                            ks * 32 + lc * 16));
            #pragma unroll
            for (int nj = 0; nj < 2; ++nj)
                ldmx4(bf[nj], base + A_STG + SWZ128((wn + nj * 16 + lr) * 128 +
                                                    ks * 32 + lc * 16));
            #pragma unroll
            for (int mi = 0; mi < 4; ++mi)
                #pragma unroll
                for (int ni = 0; ni < 4; ++ni) {
                    const int nj = ni >> 1, s = ni & 1;
                    mma16816(acc[mi][ni], af[mi], bf[nj][s], bf[nj][s + 2]);
                }
        }
    };

    load_stage(0, 0);
    load_stage(1, 1);

    const int NK = 1024 / BK;   // 16
    int st = 0;
    for (int kc = 0; kc < NK; ++kc) {
        if (kc < NK - 1)
            asm volatile("cp.async.wait_group 1;" ::: "memory");
        else
            asm volatile("cp.async.wait_group 0;" ::: "memory");
        __syncthreads();
        if (kc + 2 < NK) load_stage(kc + 2, (st + 2) % NSTAGE);
        compute(st);
        st = (st + 1) % NSTAGE;
    }

    // ---------------- epilogue ----------------
    const int qrow = lid >> 2;
    const int qcol = (lid & 3) * 2;
    const int g = (bn * 128) >> 10;
    const int ncol0 = (epi == 1) ? bn * 128 : (bn * 128) & 1023;

    if (epi == 0) {
        __half* Obase = (__half*)(g == 0 ? Oq : (g == 1 ? Ok : Ov));
        const bool do_relu = (g < 2);
        #pragma unroll
        for (int mi = 0; mi < 4; ++mi)
            #pragma unroll
            for (int ni = 0; ni < 4; ++ni) {
                const int cn = ncol0 + wn + ni * 8 + qcol;
                #pragma unroll
                for (int half = 0; half < 2; ++half) {
                    const int gm = bm * 256 + wm + mi * 16 + qrow + half * 8;
                    float v0 = acc[mi][ni][half * 2 + 0];
                    float v1 = acc[mi][ni][half * 2 + 1];
                    if (do_relu) {
                        v0 = fmaxf(v0, 0.f) + EPS;
                        v1 = fmaxf(v1, 0.f) + EPS;
                    }
                    *(__half2*)(Obase + (size_t)gm * 1024 + cn) =
                        __floats2half2_rn(v0, v1);
                }
            }
    } else {
        float* Obase = (float*)Oq;
        #pragma unroll
        for (int mi = 0; mi < 4; ++mi)
            #pragma unroll
            for (int ni = 0; ni < 4; ++ni) {
                const int cn = ncol0 + wn + ni * 8 + qcol;
                #pragma unroll
                for (int half = 0; half < 2; ++half) {
                    const int gm = bm * 256 + wm + mi * 16 + qrow + half * 8;
                    const float2 bb = *(const float2*)(bias + cn);
                    *(float2*)(Obase + (size_t)gm * 1024 + cn) =
                        make_float2(acc[mi][ni][half * 2 + 0] + bb.x,
                                    acc[mi][ni][half * 2 + 1] + bb.y);
                }
            }
    }
}

// ---------------------------------------------------------------------------
// fp32 -> fp16 convert
// ---------------------------------------------------------------------------
__global__ void acvt(const float4* __restrict__ X, __half2* __restrict__ H, int n4)
{
    int i = blockIdx.x * 256 + threadIdx.x;
    if (i >= n4) return;
    float4 v = X[i];
    H[2 * i]     = __floats2half2_rn(v.x, v.y);
    H[2 * i + 1] = __floats2half2_rn(v.z, v.w);
}

// ---------------------------------------------------------------------------
// transpose + fp16 convert of weight W[K,N] -> T[N,K]
// ---------------------------------------------------------------------------
__global__ void wtcvt(const float* __restrict__ W, __half* __restrict__ T,
                      int K, int N)
{
    __shared__ float t[32][33];
    const int n0 = blockIdx.x * 32, k0 = blockIdx.y * 32;
    const int tx = threadIdx.x, ty = threadIdx.y;
    #pragma unroll
    for (int i = 0; i < 32; i += 8)
        t[ty + i][tx] = W[(size_t)(k0 + ty + i) * N + n0 + tx];
    __syncthreads();
    #pragma unroll
    for (int i = 0; i < 32; i += 8)
        T[(size_t)(n0 + ty + i) * K + k0 + tx] = __float2half_rn(t[tx][ty + i]);
}

// ---------------------------------------------------------------------------
// kv partials + kmean partials (fp16 inputs, fp32 accumulation)
// ---------------------------------------------------------------------------
__global__ __launch_bounds__(256)
void kvmat_kernel(const __half* __restrict__ k, const __half* __restrict__ v,
                  float* __restrict__ kvp, float* __restrict__ kmp)
{
    __shared__ float Ks[32][64];
    __shared__ float Vs[32][64];
    __shared__ float sks[4][64];
    const int tid = threadIdx.x;
    const int nc = blockIdx.x, h = blockIdx.y, b = blockIdx.z;
    const int lr = tid >> 3;
    const int lc = (tid & 7) << 3;
    const int tr = (tid >> 4) << 2;
    const int tc = (tid & 15) << 2;
    const int sd = tid & 63;
    const int sg = tid >> 6;

    float acc[4][4];
    #pragma unroll
    for (int i = 0; i < 4; ++i)
        #pragma unroll
        for (int j = 0; j < 4; ++j) acc[i][j] = 0.f;
    float ks_acc = 0.f;

    const size_t base = ((size_t)(b * 4096 + nc * 256)) * 1024 + h * 64;
    for (int t = 0; t < 256; t += 32) {
        const uint4 kd = *(const uint4*)(k + base + (size_t)(t + lr) * 1024 + lc);
        const uint4 vd = *(const uint4*)(v + base + (size_t)(t + lr) * 1024 + lc);
        const __half2* kh = (const __half2*)&kd;
        const __half2* vh = (const __half2*)&vd;
        #pragma unroll
        for (int j = 0; j < 4; ++j) {
            const float2 kf = __half22float2(kh[j]);
            const float2 vf = __half22float2(vh[j]);
            Ks[lr][lc + 2 * j]     = kf.x;
            Ks[lr][lc + 2 * j + 1] = kf.y;
            Vs[lr][lc + 2 * j]     = vf.x;
            Vs[lr][lc + 2 * j + 1] = vf.y;
        }
        __syncthreads();
        #pragma unroll
        for (int nn = 0; nn < 32; ++nn) {
            float a[4], bb[4];
            *(float4*)a  = *(const float4*)&Ks[nn][tr];
            *(float4*)bb = *(const float4*)&Vs[nn][tc];
            #pragma unroll
            for (int i = 0; i < 4; ++i)
                #pragma unroll
                for (int j = 0; j < 4; ++j)
                    acc[i][j] = fmaf(a[i], bb[j], acc[i][j]);
        }
        #pragma unroll
        for (int rr = 0; rr < 8; ++rr)
            ks_acc += Ks[sg * 8 + rr][sd];
        __syncthreads();
    }
    sks[sg][sd] = ks_acc;

    float* kvo = kvp + (((size_t)(nc * 4 + b)) * 16 + h) * 4096;
    #pragma unroll
    for (int i = 0; i < 4; ++i) {
        float4 o = make_float4(acc[i][0], acc[i][1], acc[i][2], acc[i][3]);
        *(float4*)(kvo + (tr + i) * 64 + tc) = o;
    }
    __syncthreads();
    if (tid < 64)
        kmp[(size_t)(nc * 4 + b) * 1024 + h * 64 + tid] =
            sks[0][tid] + sks[1][tid] + sks[2][tid] + sks[3][tid];
}

// ---------------------------------------------------------------------------
// reduce 16 partial slices -> kv^T fp16 (scaled 1/4096) and kmean fp32
// ---------------------------------------------------------------------------
__global__ void reduce_kernel(const float* __restrict__ kvp,
                              const float* __restrict__ kmp,
                              __half* __restrict__ kvt, float* __restrict__ km)
{
    const int i = blockIdx.x * 256 + threadIdx.x;
    if (i < 262144) {
        float s = 0.f;
        #pragma unroll
        for (int nc = 0; nc < 16; ++nc) s += kvp[(size_t)nc * 262144 + i];
        const int d = (i >> 6) & 63, e = i & 63;
        kvt[(i & ~4095) + e * 64 + d] = __float2half_rn(s * (1.0f / 4096.0f));
    } else if (i < 262144 + 4096) {
        const int j = i - 262144;
        float s = 0.f;
        #pragma unroll
        for (int nc = 0; nc < 16; ++nc) s += kmp[nc * 4096 + j];
        km[j] = s * (1.0f / 4096.0f);
    }
}

// ---------------------------------------------------------------------------
// att via mma: per (b,h): att[n,e] = z_n * (q[n,:] @ kv[:,e]),
// A = q tile [128,64] fp16, B = kv^T [64,64] fp16. Writes fp16 into A16.
// 128 threads (4 warps along m), grid (32 n-tiles, 64 bh).
// ---------------------------------------------------------------------------
__global__ __launch_bounds__(128)
void att_mma(const __half* __restrict__ q, const __half* __restrict__ kvt,
             const float* __restrict__ km, __half* __restrict__ A16)
{
    __shared__ __align__(1024) char qs_raw[16384];   // 128x128B SW128
    __shared__ __align__(1024) char bs_raw[8192];    // 64x128B SW128
    __shared__ float kms[64];
    __shared__ float zs[128];

    const int tid = threadIdx.x;
    const int wid = tid >> 5, lid = tid & 31;
    const int bx = blockIdx.x, bh = blockIdx.y;
    const int b = bh >> 4, h = bh & 15;

    const uint32_t qsb = smem_u32(qs_raw);
    const uint32_t bsb = smem_u32(bs_raw);

    const size_t qbase = ((size_t)(b * 4096 + bx * 128)) * 1024 + h * 64;

    #pragma unroll
    for (int i = 0; i < 8; ++i) {
        const int idx = i * 128 + tid;
        const int r = idx >> 3, c = idx & 7;
        cpa16(qsb + SWZ128(r * 128 + c * 16), q + qbase + (size_t)r * 1024 + c * 8);
    }
    #pragma unroll
    for (int i = 0; i < 4; ++i) {
        const int idx = i * 128 + tid;
        const int r = idx >> 3, c = idx & 7;
        cpa16(bsb + SWZ128(r * 128 + c * 16), kvt + (size_t)bh * 4096 + r * 64 + c * 8);
    }
    asm volatile("cp.async.commit_group;" ::: "memory");

    if (tid < 16)
        ((float4*)kms)[tid] = ((const float4*)(km + b * 1024 + h * 64))[tid];
    __syncthreads();

    // z per row (FIXED: 8 x uint4, 8 halves each, covering d=0..63)
    {
        const __half* qr = q + qbase + (size_t)tid * 1024;
        float zd = EPS;
        #pragma unroll
        for (int i = 0; i < 8; ++i) {
            const uint4 qd = *(const uint4*)(qr + i * 8);
            const __half2* qh = (const __half2*)&qd;
            #pragma unroll
            for (int j = 0; j < 4; ++j) {
                const float2 f = __half22float2(qh[j]);
                zd = fmaf(f.x, kms[i * 8 + 2 * j],     zd);
                zd = fmaf(f.y, kms[i * 8 + 2 * j + 1], zd);
            }
        }
        zs[tid] = 1.0f / zd;
    }

    float acc[2][8][4];
    #pragma unroll
    for (int i = 0; i < 2; ++i)
        #pragma unroll
        for (int j = 0; j < 8; ++j)
            #pragma unroll
            for (int r = 0; r < 4; ++r) acc[i][j][r] = 0.f;

    asm volatile("cp.async.wait_group 0;" ::: "memory");
    __syncthreads();

    const int wm = wid * 32;
    const int lr = lid & 15, lc = lid >> 4;
    #pragma unroll
    for (int ks = 0; ks < 4; ++ks) {
        uint32_t af[2][4], bf[4][4];
        #pragma unroll
        for (int mi = 0; mi < 2; ++mi)
            ldmx4(af[mi], qsb + SWZ128((wm + mi * 16 + lr) * 128 + ks * 32 + lc * 16));
        #pragma unroll
        for (int nj = 0; nj < 4; ++nj)
            ldmx4(bf[nj], bsb + SWZ128((nj * 16 + lr) * 128 + ks * 32 + lc * 16));
        #pragma unroll
        for (int mi = 0; mi < 2; ++mi)
            #pragma unroll
            for (int ni = 0; ni < 8; ++ni) {
                const int nj = ni >> 1, s = ni & 1;
                mma16816(acc[mi][ni], af[mi], bf[nj][s], bf[nj][s + 2]);
            }
    }

    const int qrow = lid >> 2;
    const int qcol = (lid & 3) * 2;
    __half* ob = A16 + qbase;
    #pragma unroll
    for (int mi = 0; mi < 2; ++mi)
        #pragma unroll
        for (int ni = 0; ni < 8; ++ni) {
            const int cn = ni * 8 + qcol;
            #pragma unroll
            for (int half = 0; half < 2; ++half) {
                const int rm = wm + mi * 16 + qrow + half * 8;
                const float z = zs[rm];
                *(__half2*)(ob + (size_t)rm * 1024 + cn) =
                    __floats2half2_rn(acc[mi][ni][half * 2 + 0] * z,
                                      acc[mi][ni][half * 2 + 1] * z);
            }
        }
}

// ---------------------------------------------------------------------------
// depthwise 5x5 SAME conv on fp16 v; A16 += conv (fp16 RMW)
// ---------------------------------------------------------------------------
__global__ __launch_bounds__(256)
void conv_kernel(const __half* __restrict__ v, const float* __restrict__ w,
                 const float* __restrict__ wb, __half* __restrict__ A16)
{
    const int e  = threadIdx.x & 63;
    const int xg = threadIdx.x >> 6;
    const int x  = blockIdx.x * 4 + xg;
    const int y0 = blockIdx.y * 8;
    const int bh = blockIdx.z;
    const int b = bh >> 4, h = bh & 15;

    float wgt[25];
    #pragma unroll
    for (int i = 0; i < 25; ++i) wgt[i] = w[e * 25 + i];
    const float bias = wb[e];

    const size_t cofs = (size_t)b * 4096 * 1024 + h * 64 + e;
    const __half* vb = v + cofs;
    __half* ab = A16 + cofs;

    float win[5][5];
    #pragma unroll
    for (int r = 0; r < 4; ++r) {
        const int yy = y0 - 2 + r;
        #pragma unroll
        for (int c = 0; c < 5; ++c) {
            const int xx = x - 2 + c;
            win[r][c] = (yy >= 0 && yy < 64 && xx >= 0 && xx < 64)
                        ? __half2float(vb[(size_t)(yy * 64 + xx) * 1024]) : 0.f;
        }
    }

    #pragma unroll
    for (int oy = 0; oy < 8; ++oy) {
        const int yy = y0 + oy + 2;
        #pragma unroll
        for (int c = 0; c < 5; ++c) {
            const int xx = x - 2 + c;
            win[4][c] = (yy < 64 && xx >= 0 && xx < 64)
                        ? __half2float(vb[(size_t)(yy * 64 + xx) * 1024]) : 0.f;
        }
        float acc = bias;
        #pragma unroll
        for (int r = 0; r < 5; ++r)
            #pragma unroll
            for (int c = 0; c < 5; ++c)
                acc = fmaf(win[r][c], wgt[r * 5 + c], acc);

        const size_t po = (size_t)((y0 + oy) * 64 + x) * 1024;
        ab[po] = __float2half_rn(__half2float(ab[po]) + acc);

        #pragma unroll
        for (int r = 0; r < 4; ++r)
            #pragma unroll
            for (int c = 0; c < 5; ++c) win[r][c] = win[r + 1][c];
    }
}

// ---------------------------------------------------------------------------
extern "C" void kernel_launch(void* const* d_in, const int* in_sizes, int n_in,
                              void* d_out, int out_size)
{
    const float* x     = (const float*)d_in[0];
    const float* Wq    = (const float*)d_in[1];
    const float* Wkv   = (const float*)d_in[2];
    const float* Wproj = (const float*)d_in[3];
    const float* bproj = (const float*)d_in[4];
    const float* dwc_w = (const float*)d_in[5];
    const float* dwc_b = (const float*)d_in[6];
    float* out = (float*)d_out;

    float *km, *kvp, *kmp;
    __half *q16, *k16, *v16, *a16, *w16, *kvt16;
    cudaGetSymbolAddress((void**)&q16,   g_q16);
    cudaGetSymbolAddress((void**)&k16,   g_k16);
    cudaGetSymbolAddress((void**)&v16,   g_v16);
    cudaGetSymbolAddress((void**)&km,    g_kmean);
    cudaGetSymbolAddress((void**)&kvt16, g_kvt16);
    cudaGetSymbolAddress((void**)&kvp,   g_kvp);
    cudaGetSymbolAddress((void**)&kmp,   g_kmp);
    cudaGetSymbolAddress((void**)&a16,   g_a16);
    cudaGetSymbolAddress((void**)&w16,   g_w16);

    cudaFuncSetAttribute(mma_gemm, cudaFuncAttributeMaxDynamicSharedMemorySize,
                         NSTAGE * STG);

    acvt<<<16384, 256>>>((const float4*)x, (__half2*)a16, 4194304);
    wtcvt<<<dim3(32, 32), dim3(32, 8)>>>(Wq,    w16,           1024, 1024);
    wtcvt<<<dim3(64, 32), dim3(32, 8)>>>(Wkv,   w16 + 1048576, 1024, 2048);
    wtcvt<<<dim3(32, 32), dim3(32, 8)>>>(Wproj, w16 + 3145728, 1024, 1024);

    const size_t smem = NSTAGE * STG;
    // merged q/k/v GEMM: N=3072 -> fp16 q,k,v  (M-tiles of 256)
    mma_gemm<<<dim3(24, 64), 512, smem>>>(a16, w16, q16, k16, v16, nullptr, 0);

    kvmat_kernel<<<dim3(16, 16, 4), 256>>>(k16, v16, kvp, kmp);
    reduce_kernel<<<1040, 256>>>(kvp, kmp, kvt16, km);
    att_mma<<<dim3(32, 64), 128>>>(q16, kvt16, km, a16);
    conv_kernel<<<dim3(16, 8, 64), 256>>>(v16, dwc_w, dwc_b, a16);

    // out = (att+conv) @ Wproj + bproj  (fp32 out)
    mma_gemm<<<dim3(8, 64), 512, smem>>>(a16, w16 + 3145728, out, nullptr,
                                         nullptr, bproj, 1);
}

// round 9
// speedup vs baseline: 2.6069x; 1.1408x over previous
#include <cuda_runtime.h>
#include <cuda_fp16.h>
#include <cstdint>

#define EPS 1e-6f

// ---------------- scratch (__device__ globals; no allocations allowed) -----
__device__ __half g_q16[16777216];   // (16384,1024) fp16
__device__ __half g_k16[16777216];
__device__ __half g_v16[16777216];
__device__ float g_kmean[4096];      // (B,1024)
__device__ __half g_kvt16[262144];   // kv^T fp16: [b,h][e][d]
__device__ float g_kvp[1048576];     // kv partials: [4 nc][B][h][64][64]
__device__ float g_kmp[65536];       // kmean partials: [16 sl][B][1024]
__device__ __half g_a16[16777216];   // A operand fp16 (x, then att+conv)
__device__ __half g_w16[4194304];    // transposed weights fp16 [WqT|WkvT|WprojT]

// ---------------- PTX helpers (baseline sm_80+ features only) --------------
__device__ __forceinline__ uint32_t smem_u32(const void* p) {
    uint32_t a;
    asm("{ .reg .u64 t; cvta.to.shared.u64 t, %1; cvt.u32.u64 %0, t; }"
        : "=r"(a) : "l"(p));
    return a;
}
__device__ __forceinline__ void cpa16(uint32_t s, const void* g) {
    asm volatile("cp.async.cg.shared.global [%0], [%1], 16;" :: "r"(s), "l"(g));
}
__device__ __forceinline__ void ldmx4(uint32_t* r, uint32_t a) {
    asm volatile("ldmatrix.sync.aligned.m8n8.x4.shared.b16 {%0,%1,%2,%3}, [%4];"
                 : "=r"(r[0]), "=r"(r[1]), "=r"(r[2]), "=r"(r[3]) : "r"(a));
}
__device__ __forceinline__ void ldmx4t(uint32_t* r, uint32_t a) {
    asm volatile("ldmatrix.sync.aligned.m8n8.x4.trans.shared.b16 {%0,%1,%2,%3}, [%4];"
                 : "=r"(r[0]), "=r"(r[1]), "=r"(r[2]), "=r"(r[3]) : "r"(a));
}
__device__ __forceinline__ void mma16816(float* c, const uint32_t* a,
                                         uint32_t b0, uint32_t b1) {
    asm volatile(
        "mma.sync.aligned.m16n8k16.row.col.f32.f16.f16.f32 "
        "{%0,%1,%2,%3},{%4,%5,%6,%7},{%8,%9},{%0,%1,%2,%3};"
        : "+f"(c[0]), "+f"(c[1]), "+f"(c[2]), "+f"(c[3])
        : "r"(a[0]), "r"(a[1]), "r"(a[2]), "r"(a[3]), "r"(b0), "r"(b1));
}
#define SWZ128(o) ((o) ^ (((o) >> 3) & 0x70))

// ---------------------------------------------------------------------------
// fp16 single-pass GEMM: D(fp32 acc) = A * B^T   (round-6 winning shape)
// CTA tile 128x128, BK=64 (128B rows, SW128), 256 threads (8 warps: 2m x 4n,
// warp tile 64x32), 3-stage cp.async ring, one __syncthreads per K-chunk.
// epi 0: qkv split -> fp16 (group g: 0 relu->Oq, 1 relu->Ok, 2 raw->Ov)
// epi 1: +bias -> fp32 Oq. Output ld = 1024.
// ---------------------------------------------------------------------------
#define BK 64
#define TSTG 16384                // 128 rows x 128B
#define STG (2 * TSTG)            // A|B per stage = 32KB
#define NSTAGE 3

__global__ __launch_bounds__(256, 2)
void mma_gemm(const __half* __restrict__ A, const __half* __restrict__ B,
              void* __restrict__ Oq, void* __restrict__ Ok,
              void* __restrict__ Ov, const float* __restrict__ bias, int epi)
{
    extern __shared__ __align__(1024) char smraw[];
    const uint32_t sb = smem_u32(smraw);

    const int tid = threadIdx.x;
    const int wid = tid >> 5, lid = tid & 31;
    const int bm = blockIdx.y, bn = blockIdx.x;

    const int wm = (wid & 1) * 64;    // 2 warps along m
    const int wn = (wid >> 1) * 32;   // 4 warps along n
    const int lr = lid & 15, lc = lid >> 4;

    float acc[4][4][4];
    #pragma unroll
    for (int i = 0; i < 4; ++i)
        #pragma unroll
        for (int j = 0; j < 4; ++j)
            #pragma unroll
            for (int r = 0; r < 4; ++r) acc[i][j][r] = 0.f;

    auto load_stage = [&](int kc, int st) {
        const uint32_t base = sb + st * STG;
        const int kofs = kc * BK;
        #pragma unroll
        for (int i = 0; i < 4; ++i) {
            const int idx = i * 256 + tid;
            const int r = idx >> 3, c = idx & 7;
            const uint32_t so = SWZ128(r * 128 + c * 16);
            cpa16(base + so,        A + (size_t)(bm * 128 + r) * 1024 + kofs + c * 8);
            cpa16(base + TSTG + so, B + (size_t)(bn * 128 + r) * 1024 + kofs + c * 8);
        }
        asm volatile("cp.async.commit_group;" ::: "memory");
    };

    auto compute = [&](int st) {
        const uint32_t base = sb + st * STG;
        #pragma unroll
        for (int ks = 0; ks < 4; ++ks) {
            uint32_t af[4][4], bf[2][4];
            #pragma unroll
            for (int mi = 0; mi < 4; ++mi)
                ldmx4(af[mi], base + SWZ128((wm + mi * 16 + lr) * 128 +
                                            ks * 32 + lc * 16));
            #pragma unroll
            for (int nj = 0; nj < 2; ++nj)
                ldmx4(bf[nj], base + TSTG + SWZ128((wn + nj * 16 + lr) * 128 +
                                                   ks * 32 + lc * 16));
            #pragma unroll
            for (int mi = 0; mi < 4; ++mi)
                #pragma unroll
                for (int ni = 0; ni < 4; ++ni) {
                    const int nj = ni >> 1, s = ni & 1;
                    mma16816(acc[mi][ni], af[mi], bf[nj][s], bf[nj][s + 2]);
                }
        }
    };

    load_stage(0, 0);
    load_stage(1, 1);

    const int NK = 1024 / BK;   // 16
    int st = 0;
    for (int kc = 0; kc < NK; ++kc) {
        if (kc < NK - 1)
            asm volatile("cp.async.wait_group 1;" ::: "memory");
        else
            asm volatile("cp.async.wait_group 0;" ::: "memory");
        __syncthreads();
        if (kc + 2 < NK) load_stage(kc + 2, (st + 2) % NSTAGE);
        compute(st);
        st = (st + 1) % NSTAGE;
    }

    // ---------------- epilogue ----------------
    const int qrow = lid >> 2;
    const int qcol = (lid & 3) * 2;
    const int g = (bn * 128) >> 10;
    const int ncol0 = (epi == 1) ? bn * 128 : (bn * 128) & 1023;

    if (epi == 0) {
        __half* Obase = (__half*)(g == 0 ? Oq : (g == 1 ? Ok : Ov));
        const bool do_relu = (g < 2);
        #pragma unroll
        for (int mi = 0; mi < 4; ++mi)
            #pragma unroll
            for (int ni = 0; ni < 4; ++ni) {
                const int cn = ncol0 + wn + ni * 8 + qcol;
                #pragma unroll
                for (int half = 0; half < 2; ++half) {
                    const int gm = bm * 128 + wm + mi * 16 + qrow + half * 8;
                    float v0 = acc[mi][ni][half * 2 + 0];
                    float v1 = acc[mi][ni][half * 2 + 1];
                    if (do_relu) {
                        v0 = fmaxf(v0, 0.f) + EPS;
                        v1 = fmaxf(v1, 0.f) + EPS;
                    }
                    *(__half2*)(Obase + (size_t)gm * 1024 + cn) =
                        __floats2half2_rn(v0, v1);
                }
            }
    } else {
        float* Obase = (float*)Oq;
        #pragma unroll
        for (int mi = 0; mi < 4; ++mi)
            #pragma unroll
            for (int ni = 0; ni < 4; ++ni) {
                const int cn = ncol0 + wn + ni * 8 + qcol;
                #pragma unroll
                for (int half = 0; half < 2; ++half) {
                    const int gm = bm * 128 + wm + mi * 16 + qrow + half * 8;
                    const float2 bb = *(const float2*)(bias + cn);
                    *(float2*)(Obase + (size_t)gm * 1024 + cn) =
                        make_float2(acc[mi][ni][half * 2 + 0] + bb.x,
                                    acc[mi][ni][half * 2 + 1] + bb.y);
                }
            }
    }
}

// ---------------------------------------------------------------------------
// fp32 -> fp16 convert
// ---------------------------------------------------------------------------
__global__ void acvt(const float4* __restrict__ X, __half2* __restrict__ H, int n4)
{
    int i = blockIdx.x * 256 + threadIdx.x;
    if (i >= n4) return;
    float4 v = X[i];
    H[2 * i]     = __floats2half2_rn(v.x, v.y);
    H[2 * i + 1] = __floats2half2_rn(v.z, v.w);
}

// ---------------------------------------------------------------------------
// transpose + fp16 convert of weight W[K,N] -> T[N,K]
// ---------------------------------------------------------------------------
__global__ void wtcvt(const float* __restrict__ W, __half* __restrict__ T,
                      int K, int N)
{
    __shared__ float t[32][33];
    const int n0 = blockIdx.x * 32, k0 = blockIdx.y * 32;
    const int tx = threadIdx.x, ty = threadIdx.y;
    #pragma unroll
    for (int i = 0; i < 32; i += 8)
        t[ty + i][tx] = W[(size_t)(k0 + ty + i) * N + n0 + tx];
    __syncthreads();
    #pragma unroll
    for (int i = 0; i < 32; i += 8)
        T[(size_t)(n0 + ty + i) * K + k0 + tx] = __float2half_rn(t[tx][ty + i]);
}

// ---------------------------------------------------------------------------
// kmean partials: kmp[sl*4+b][c] = sum over 256-row slice of k[b,n,c]
// ---------------------------------------------------------------------------
__global__ void ksum_kernel(const __half* __restrict__ k, float* __restrict__ kmp)
{
    const int c = blockIdx.x * 256 + threadIdx.x;
    const int b = blockIdx.y;
    const int sl = blockIdx.z;
    const __half* p = k + ((size_t)(b * 4096 + sl * 256)) * 1024 + c;
    float s = 0.f;
    #pragma unroll 8
    for (int n = 0; n < 256; ++n) s += __half2float(p[(size_t)n * 1024]);
    kmp[(size_t)(sl * 4 + b) * 1024 + c] = s;
}

// ---------------------------------------------------------------------------
// kv partials via tensor cores: kvp[nc][b][h][d][e] = sum_n k[n,d]*v[n,e]
// over the block's 1024-row n-chunk. Both operands need transposed fragments
// (reduction over the row index) -> ldmatrix.x4.trans on SW128 tiles.
// 128 threads (4 warps: warp w owns d rows w*16..+15), grid (4 nc, 16 h, 4 b).
// ---------------------------------------------------------------------------
#define KVT 8192   // one 64x64 fp16 tile

__global__ __launch_bounds__(128)
void kvmat_mma(const __half* __restrict__ k, const __half* __restrict__ v,
               float* __restrict__ kvp)
{
    __shared__ __align__(1024) char kvs_raw[4 * KVT];   // 2 bufs x (k|v)
    const uint32_t sb = smem_u32(kvs_raw);

    const int tid = threadIdx.x;
    const int wid = tid >> 5, lid = tid & 31;
    const int nc = blockIdx.x, h = blockIdx.y, b = blockIdx.z;

    const size_t base = ((size_t)(b * 4096 + nc * 1024)) * 1024 + h * 64;

    auto load_sc = [&](int sc, int buf) {
        const uint32_t kb = sb + buf * 2 * KVT;
        #pragma unroll
        for (int i = 0; i < 4; ++i) {
            const int idx = i * 128 + tid;
            const int r = idx >> 3, c = idx & 7;
            const size_t go = base + (size_t)(sc * 64 + r) * 1024 + c * 8;
            const uint32_t so = SWZ128(r * 128 + c * 16);
            cpa16(kb + so, k + go);
            cpa16(kb + KVT + so, v + go);
        }
        asm volatile("cp.async.commit_group;" ::: "memory");
    };

    float acc[8][4];
    #pragma unroll
    for (int i = 0; i < 8; ++i)
        #pragma unroll
        for (int r = 0; r < 4; ++r) acc[i][r] = 0.f;

    // ldmatrix.trans lane addressing: row = stored n-row, col = d (A) / e (B)
    const int trow  = ((lid >> 4) << 3) + (lid & 7);   // +0/8 n-row block
    const int tcolh = ((lid >> 3) & 1) << 3;           // +0/8 col halves

    load_sc(0, 0);
    for (int sc = 0; sc < 16; ++sc) {
        const int buf = sc & 1;
        if (sc < 15) {
            load_sc(sc + 1, buf ^ 1);
            asm volatile("cp.async.wait_group 1;" ::: "memory");
        } else {
            asm volatile("cp.async.wait_group 0;" ::: "memory");
        }
        __syncthreads();
        const uint32_t kb = sb + buf * 2 * KVT;
        #pragma unroll
        for (int ks = 0; ks < 4; ++ks) {
            uint32_t af[4], bf[4][4];
            ldmx4t(af, kb + SWZ128((ks * 16 + trow) * 128 +
                                   (wid * 16 + tcolh) * 2));
            #pragma unroll
            for (int nj = 0; nj < 4; ++nj)
                ldmx4t(bf[nj], kb + KVT + SWZ128((ks * 16 + trow) * 128 +
                                                 (nj * 16 + tcolh) * 2));
            #pragma unroll
            for (int ni = 0; ni < 8; ++ni) {
                const int nj = ni >> 1, s = ni & 1;
                mma16816(acc[ni], af, bf[nj][s], bf[nj][s + 2]);
            }
        }
        __syncthreads();
    }

    const int qrow = lid >> 2;
    const int qcol = (lid & 3) * 2;
    float* kvo = kvp + (((size_t)(nc * 4 + b)) * 16 + h) * 4096;
    #pragma unroll
    for (int ni = 0; ni < 8; ++ni)
        #pragma unroll
        for (int half = 0; half < 2; ++half) {
            const int dm = wid * 16 + qrow + half * 8;
            *(float2*)(kvo + dm * 64 + ni * 8 + qcol) =
                make_float2(acc[ni][half * 2 + 0], acc[ni][half * 2 + 1]);
        }
}

// ---------------------------------------------------------------------------
// reduce partials -> kv^T fp16 (scaled 1/4096) and kmean fp32
// ---------------------------------------------------------------------------
__global__ void reduce_kernel(const float* __restrict__ kvp,
                              const float* __restrict__ kmp,
                              __half* __restrict__ kvt, float* __restrict__ km)
{
    const int i = blockIdx.x * 256 + threadIdx.x;
    if (i < 262144) {
        float s = 0.f;
        #pragma unroll
        for (int nc = 0; nc < 4; ++nc) s += kvp[(size_t)nc * 262144 + i];
        const int d = (i >> 6) & 63, e = i & 63;
        kvt[(i & ~4095) + e * 64 + d] = __float2half_rn(s * (1.0f / 4096.0f));
    } else if (i < 262144 + 4096) {
        const int j = i - 262144;
        float s = 0.f;
        #pragma unroll
        for (int sl = 0; sl < 16; ++sl) s += kmp[sl * 4096 + j];
        km[j] = s * (1.0f / 4096.0f);
    }
}

// ---------------------------------------------------------------------------
// att via mma: per (b,h): att[n,e] = z_n * (q[n,:] @ kv[:,e]),
// A = q tile [128,64] fp16, B = kv^T [64,64] fp16. Writes fp16 into A16.
// ---------------------------------------------------------------------------
__global__ __launch_bounds__(128)
void att_mma(const __half* __restrict__ q, const __half* __restrict__ kvt,
             const float* __restrict__ km, __half* __restrict__ A16)
{
    __shared__ __align__(1024) char qs_raw[16384];   // 128x128B SW128
    __shared__ __align__(1024) char bs_raw[8192];    // 64x128B SW128
    __shared__ float kms[64];
    __shared__ float zs[128];

    const int tid = threadIdx.x;
    const int wid = tid >> 5, lid = tid & 31;
    const int bx = blockIdx.x, bh = blockIdx.y;
    const int b = bh >> 4, h = bh & 15;

    const uint32_t qsb = smem_u32(qs_raw);
    const uint32_t bsb = smem_u32(bs_raw);

    const size_t qbase = ((size_t)(b * 4096 + bx * 128)) * 1024 + h * 64;

    #pragma unroll
    for (int i = 0; i < 8; ++i) {
        const int idx = i * 128 + tid;
        const int r = idx >> 3, c = idx & 7;
        cpa16(qsb + SWZ128(r * 128 + c * 16), q + qbase + (size_t)r * 1024 + c * 8);
    }
    #pragma unroll
    for (int i = 0; i < 4; ++i) {
        const int idx = i * 128 + tid;
        const int r = idx >> 3, c = idx & 7;
        cpa16(bsb + SWZ128(r * 128 + c * 16), kvt + (size_t)bh * 4096 + r * 64 + c * 8);
    }
    asm volatile("cp.async.commit_group;" ::: "memory");

    if (tid < 16)
        ((float4*)kms)[tid] = ((const float4*)(km + b * 1024 + h * 64))[tid];
    __syncthreads();

    {
        const __half* qr = q + qbase + (size_t)tid * 1024;
        float zd = EPS;
        #pragma unroll
        for (int i = 0; i < 8; ++i) {
            const uint4 qd = *(const uint4*)(qr + i * 8);
            const __half2* qh = (const __half2*)&qd;
            #pragma unroll
            for (int j = 0; j < 4; ++j) {
                const float2 f = __half22float2(qh[j]);
                zd = fmaf(f.x, kms[i * 8 + 2 * j],     zd);
                zd = fmaf(f.y, kms[i * 8 + 2 * j + 1], zd);
            }
        }
        zs[tid] = 1.0f / zd;
    }

    float acc[2][8][4];
    #pragma unroll
    for (int i = 0; i < 2; ++i)
        #pragma unroll
        for (int j = 0; j < 8; ++j)
            #pragma unroll
            for (int r = 0; r < 4; ++r) acc[i][j][r] = 0.f;

    asm volatile("cp.async.wait_group 0;" ::: "memory");
    __syncthreads();

    const int wm = wid * 32;
    const int lr = lid & 15, lc = lid >> 4;
    #pragma unroll
    for (int ks = 0; ks < 4; ++ks) {
        uint32_t af[2][4], bf[4][4];
        #pragma unroll
        for (int mi = 0; mi < 2; ++mi)
            ldmx4(af[mi], qsb + SWZ128((wm + mi * 16 + lr) * 128 + ks * 32 + lc * 16));
        #pragma unroll
        for (int nj = 0; nj < 4; ++nj)
            ldmx4(bf[nj], bsb + SWZ128((nj * 16 + lr) * 128 + ks * 32 + lc * 16));
        #pragma unroll
        for (int mi = 0; mi < 2; ++mi)
            #pragma unroll
            for (int ni = 0; ni < 8; ++ni) {
                const int nj = ni >> 1, s = ni & 1;
                mma16816(acc[mi][ni], af[mi], bf[nj][s], bf[nj][s + 2]);
            }
    }

    const int qrow = lid >> 2;
    const int qcol = (lid & 3) * 2;
    __half* ob = A16 + qbase;
    #pragma unroll
    for (int mi = 0; mi < 2; ++mi)
        #pragma unroll
        for (int ni = 0; ni < 8; ++ni) {
            const int cn = ni * 8 + qcol;
            #pragma unroll
            for (int half = 0; half < 2; ++half) {
                const int rm = wm + mi * 16 + qrow + half * 8;
                const float z = zs[rm];
                *(__half2*)(ob + (size_t)rm * 1024 + cn) =
                    __floats2half2_rn(acc[mi][ni][half * 2 + 0] * z,
                                      acc[mi][ni][half * 2 + 1] * z);
            }
        }
}

// ---------------------------------------------------------------------------
// depthwise 5x5 SAME conv on fp16 v; A16 += conv (fp16 RMW)
// ---------------------------------------------------------------------------
__global__ __launch_bounds__(256)
void conv_kernel(const __half* __restrict__ v, const float* __restrict__ w,
                 const float* __restrict__ wb, __half* __restrict__ A16)
{
    const int e  = threadIdx.x & 63;
    const int xg = threadIdx.x >> 6;
    const int x  = blockIdx.x * 4 + xg;
    const int y0 = blockIdx.y * 8;
    const int bh = blockIdx.z;
    const int b = bh >> 4, h = bh & 15;

    float wgt[25];
    #pragma unroll
    for (int i = 0; i < 25; ++i) wgt[i] = w[e * 25 + i];
    const float bias = wb[e];

    const size_t cofs = (size_t)b * 4096 * 1024 + h * 64 + e;
    const __half* vb = v + cofs;
    __half* ab = A16 + cofs;

    float win[5][5];
    #pragma unroll
    for (int r = 0; r < 4; ++r) {
        const int yy = y0 - 2 + r;
        #pragma unroll
        for (int c = 0; c < 5; ++c) {
            const int xx = x - 2 + c;
            win[r][c] = (yy >= 0 && yy < 64 && xx >= 0 && xx < 64)
                        ? __half2float(vb[(size_t)(yy * 64 + xx) * 1024]) : 0.f;
        }
    }

    #pragma unroll
    for (int oy = 0; oy < 8; ++oy) {
        const int yy = y0 + oy + 2;
        #pragma unroll
        for (int c = 0; c < 5; ++c) {
            const int xx = x - 2 + c;
            win[4][c] = (yy < 64 && xx >= 0 && xx < 64)
                        ? __half2float(vb[(size_t)(yy * 64 + xx) * 1024]) : 0.f;
        }
        float acc = bias;
        #pragma unroll
        for (int r = 0; r < 5; ++r)
            #pragma unroll
            for (int c = 0; c < 5; ++c)
                acc = fmaf(win[r][c], wgt[r * 5 + c], acc);

        const size_t po = (size_t)((y0 + oy) * 64 + x) * 1024;
        ab[po] = __float2half_rn(__half2float(ab[po]) + acc);

        #pragma unroll
        for (int r = 0; r < 4; ++r)
            #pragma unroll
            for (int c = 0; c < 5; ++c) win[r][c] = win[r + 1][c];
    }
}

// ---------------------------------------------------------------------------
extern "C" void kernel_launch(void* const* d_in, const int* in_sizes, int n_in,
                              void* d_out, int out_size)
{
    const float* x     = (const float*)d_in[0];
    const float* Wq    = (const float*)d_in[1];
    const float* Wkv   = (const float*)d_in[2];
    const float* Wproj = (const float*)d_in[3];
    const float* bproj = (const float*)d_in[4];
    const float* dwc_w = (const float*)d_in[5];
    const float* dwc_b = (const float*)d_in[6];
    float* out = (float*)d_out;

    float *km, *kvp, *kmp;
    __half *q16, *k16, *v16, *a16, *w16, *kvt16;
    cudaGetSymbolAddress((void**)&q16,   g_q16);
    cudaGetSymbolAddress((void**)&k16,   g_k16);
    cudaGetSymbolAddress((void**)&v16,   g_v16);
    cudaGetSymbolAddress((void**)&km,    g_kmean);
    cudaGetSymbolAddress((void**)&kvt16, g_kvt16);
    cudaGetSymbolAddress((void**)&kvp,   g_kvp);
    cudaGetSymbolAddress((void**)&kmp,   g_kmp);
    cudaGetSymbolAddress((void**)&a16,   g_a16);
    cudaGetSymbolAddress((void**)&w16,   g_w16);

    cudaFuncSetAttribute(mma_gemm, cudaFuncAttributeMaxDynamicSharedMemorySize,
                         NSTAGE * STG);

    acvt<<<16384, 256>>>((const float4*)x, (__half2*)a16, 4194304);
    wtcvt<<<dim3(32, 32), dim3(32, 8)>>>(Wq,    w16,           1024, 1024);
    wtcvt<<<dim3(64, 32), dim3(32, 8)>>>(Wkv,   w16 + 1048576, 1024, 2048);
    wtcvt<<<dim3(32, 32), dim3(32, 8)>>>(Wproj, w16 + 3145728, 1024, 1024);

    const size_t smem = NSTAGE * STG;
    // merged q/k/v GEMM: N=3072 -> fp16 q,k,v
    mma_gemm<<<dim3(24, 128), 256, smem>>>(a16, w16, q16, k16, v16, nullptr, 0);

    ksum_kernel<<<dim3(4, 4, 16), 256>>>(k16, kmp);
    kvmat_mma<<<dim3(4, 16, 4), 128>>>(k16, v16, kvp);
    reduce_kernel<<<1040, 256>>>(kvp, kmp, kvt16, km);
    att_mma<<<dim3(32, 64), 128>>>(q16, kvt16, km, a16);
    conv_kernel<<<dim3(16, 8, 64), 256>>>(v16, dwc_w, dwc_b, a16);

    // out = (att+conv) @ Wproj + bproj  (fp32 out)
    mma_gemm<<<dim3(8, 128), 256, smem>>>(a16, w16 + 3145728, out, nullptr,
                                          nullptr, bproj, 1);
}

// round 10
// speedup vs baseline: 2.7037x; 1.0371x over previous
#include <cuda_runtime.h>
#include <cuda_fp16.h>
#include <cstdint>

#define EPS 1e-6f

// ---------------- scratch (__device__ globals; no allocations allowed) -----
__device__ __half g_q16[16777216];   // (16384,1024) fp16
__device__ __half g_k16[16777216];
__device__ __half g_v16[16777216];
__device__ float g_kmean[4096];      // (B,1024)
__device__ __half g_kvt16[262144];   // kv^T fp16: [b,h][e][d]
__device__ float g_kvp[1048576];     // kv partials: [4 nc][B][h][64][64]
__device__ float g_kmp[16384];       // kmean partials: [4 nc][B][1024]
__device__ __half g_a16[16777216];   // A operand fp16 (x, then att+conv)
__device__ __half g_w16[4194304];    // transposed weights fp16 [WqT|WkvT|WprojT]

// ---------------- PTX helpers (baseline sm_80+ features only) --------------
__device__ __forceinline__ uint32_t smem_u32(const void* p) {
    uint32_t a;
    asm("{ .reg .u64 t; cvta.to.shared.u64 t, %1; cvt.u32.u64 %0, t; }"
        : "=r"(a) : "l"(p));
    return a;
}
__device__ __forceinline__ void cpa16(uint32_t s, const void* g) {
    asm volatile("cp.async.cg.shared.global [%0], [%1], 16;" :: "r"(s), "l"(g));
}
__device__ __forceinline__ void ldmx4(uint32_t* r, uint32_t a) {
    asm volatile("ldmatrix.sync.aligned.m8n8.x4.shared.b16 {%0,%1,%2,%3}, [%4];"
                 : "=r"(r[0]), "=r"(r[1]), "=r"(r[2]), "=r"(r[3]) : "r"(a));
}
__device__ __forceinline__ void ldmx4t(uint32_t* r, uint32_t a) {
    asm volatile("ldmatrix.sync.aligned.m8n8.x4.trans.shared.b16 {%0,%1,%2,%3}, [%4];"
                 : "=r"(r[0]), "=r"(r[1]), "=r"(r[2]), "=r"(r[3]) : "r"(a));
}
__device__ __forceinline__ void mma16816(float* c, const uint32_t* a,
                                         uint32_t b0, uint32_t b1) {
    asm volatile(
        "mma.sync.aligned.m16n8k16.row.col.f32.f16.f16.f32 "
        "{%0,%1,%2,%3},{%4,%5,%6,%7},{%8,%9},{%0,%1,%2,%3};"
        : "+f"(c[0]), "+f"(c[1]), "+f"(c[2]), "+f"(c[3])
        : "r"(a[0]), "r"(a[1]), "r"(a[2]), "r"(a[3]), "r"(b0), "r"(b1));
}
#define SWZ128(o) ((o) ^ (((o) >> 3) & 0x70))

// ---------------------------------------------------------------------------
// fp16 single-pass GEMM: D(fp32 acc) = A * B^T
// CTA tile 128x128, BK=64 (128B rows, SW128), 256 threads (8 warps: 2m x 4n,
// warp tile 64x32), 3-stage cp.async ring, one __syncthreads per K-chunk.
// epi 0: qkv split -> fp16 (group g: 0 relu->Oq, 1 relu->Ok, 2 raw->Ov)
// epi 1: +bias -> fp32 Oq. Output ld = 1024.
// ---------------------------------------------------------------------------
#define BK 64
#define TSTG 16384                // 128 rows x 128B
#define STG (2 * TSTG)            // A|B per stage = 32KB
#define NSTAGE 3

__global__ __launch_bounds__(256, 2)
void mma_gemm(const __half* __restrict__ A, const __half* __restrict__ B,
              void* __restrict__ Oq, void* __restrict__ Ok,
              void* __restrict__ Ov, const float* __restrict__ bias, int epi)
{
    extern __shared__ __align__(1024) char smraw[];
    const uint32_t sb = smem_u32(smraw);

    const int tid = threadIdx.x;
    const int wid = tid >> 5, lid = tid & 31;
    const int bm = blockIdx.y, bn = blockIdx.x;

    const int wm = (wid & 1) * 64;    // 2 warps along m
    const int wn = (wid >> 1) * 32;   // 4 warps along n
    const int lr = lid & 15, lc = lid >> 4;

    float acc[4][4][4];
    #pragma unroll
    for (int i = 0; i < 4; ++i)
        #pragma unroll
        for (int j = 0; j < 4; ++j)
            #pragma unroll
            for (int r = 0; r < 4; ++r) acc[i][j][r] = 0.f;

    auto load_stage = [&](int kc, int st) {
        const uint32_t base = sb + st * STG;
        const int kofs = kc * BK;
        #pragma unroll
        for (int i = 0; i < 4; ++i) {
            const int idx = i * 256 + tid;
            const int r = idx >> 3, c = idx & 7;
            const uint32_t so = SWZ128(r * 128 + c * 16);
            cpa16(base + so,        A + (size_t)(bm * 128 + r) * 1024 + kofs + c * 8);
            cpa16(base + TSTG + so, B + (size_t)(bn * 128 + r) * 1024 + kofs + c * 8);
        }
        asm volatile("cp.async.commit_group;" ::: "memory");
    };

    auto compute = [&](int st) {
        const uint32_t base = sb + st * STG;
        #pragma unroll
        for (int ks = 0; ks < 4; ++ks) {
            uint32_t af[4][4], bf[2][4];
            #pragma unroll
            for (int mi = 0; mi < 4; ++mi)
                ldmx4(af[mi], base + SWZ128((wm + mi * 16 + lr) * 128 +
                                            ks * 32 + lc * 16));
            #pragma unroll
            for (int nj = 0; nj < 2; ++nj)
                ldmx4(bf[nj], base + TSTG + SWZ128((wn + nj * 16 + lr) * 128 +
                                                   ks * 32 + lc * 16));
            #pragma unroll
            for (int mi = 0; mi < 4; ++mi)
                #pragma unroll
                for (int ni = 0; ni < 4; ++ni) {
                    const int nj = ni >> 1, s = ni & 1;
                    mma16816(acc[mi][ni], af[mi], bf[nj][s], bf[nj][s + 2]);
                }
        }
    };

    load_stage(0, 0);
    load_stage(1, 1);

    const int NK = 1024 / BK;   // 16
    int st = 0;
    for (int kc = 0; kc < NK; ++kc) {
        if (kc < NK - 1)
            asm volatile("cp.async.wait_group 1;" ::: "memory");
        else
            asm volatile("cp.async.wait_group 0;" ::: "memory");
        __syncthreads();
        if (kc + 2 < NK) load_stage(kc + 2, (st + 2) % NSTAGE);
        compute(st);
        st = (st + 1) % NSTAGE;
    }

    // ---------------- epilogue ----------------
    const int qrow = lid >> 2;
    const int qcol = (lid & 3) * 2;
    const int g = (bn * 128) >> 10;
    const int ncol0 = (epi == 1) ? bn * 128 : (bn * 128) & 1023;

    if (epi == 0) {
        __half* Obase = (__half*)(g == 0 ? Oq : (g == 1 ? Ok : Ov));
        const bool do_relu = (g < 2);
        #pragma unroll
        for (int mi = 0; mi < 4; ++mi)
            #pragma unroll
            for (int ni = 0; ni < 4; ++ni) {
                const int cn = ncol0 + wn + ni * 8 + qcol;
                #pragma unroll
                for (int half = 0; half < 2; ++half) {
                    const int gm = bm * 128 + wm + mi * 16 + qrow + half * 8;
                    float v0 = acc[mi][ni][half * 2 + 0];
                    float v1 = acc[mi][ni][half * 2 + 1];
                    if (do_relu) {
                        v0 = fmaxf(v0, 0.f) + EPS;
                        v1 = fmaxf(v1, 0.f) + EPS;
                    }
                    *(__half2*)(Obase + (size_t)gm * 1024 + cn) =
                        __floats2half2_rn(v0, v1);
                }
            }
    } else {
        float* Obase = (float*)Oq;
        #pragma unroll
        for (int mi = 0; mi < 4; ++mi)
            #pragma unroll
            for (int ni = 0; ni < 4; ++ni) {
                const int cn = ncol0 + wn + ni * 8 + qcol;
                #pragma unroll
                for (int half = 0; half < 2; ++half) {
                    const int gm = bm * 128 + wm + mi * 16 + qrow + half * 8;
                    const float2 bb = *(const float2*)(bias + cn);
                    *(float2*)(Obase + (size_t)gm * 1024 + cn) =
                        make_float2(acc[mi][ni][half * 2 + 0] + bb.x,
                                    acc[mi][ni][half * 2 + 1] + bb.y);
                }
            }
    }
}

// ---------------------------------------------------------------------------
// fp32 -> fp16 convert
// ---------------------------------------------------------------------------
__global__ void acvt(const float4* __restrict__ X, __half2* __restrict__ H, int n4)
{
    int i = blockIdx.x * 256 + threadIdx.x;
    if (i >= n4) return;
    float4 v = X[i];
    H[2 * i]     = __floats2half2_rn(v.x, v.y);
    H[2 * i + 1] = __floats2half2_rn(v.z, v.w);
}

// ---------------------------------------------------------------------------
// transpose + fp16 convert of weight W[K,N] -> T[N,K]
// ---------------------------------------------------------------------------
__global__ void wtcvt(const float* __restrict__ W, __half* __restrict__ T,
                      int K, int N)
{
    __shared__ float t[32][33];
    const int n0 = blockIdx.x * 32, k0 = blockIdx.y * 32;
    const int tx = threadIdx.x, ty = threadIdx.y;
    #pragma unroll
    for (int i = 0; i < 32; i += 8)
        t[ty + i][tx] = W[(size_t)(k0 + ty + i) * N + n0 + tx];
    __syncthreads();
    #pragma unroll
    for (int i = 0; i < 32; i += 8)
        T[(size_t)(n0 + ty + i) * K + k0 + tx] = __float2half_rn(t[tx][ty + i]);
}

// ---------------------------------------------------------------------------
// kv partials via tensor cores + fused k-column sums:
// kvp[nc][b][h][d][e] = sum_n k[n,d]*v[n,e] over the block's 1024-row chunk,
// kmp[nc][b][h*64+e]  = sum_n k[n,e] over the same chunk.
// Both mma operands need transposed fragments -> ldmatrix.x4.trans.
// 128 threads (4 warps), grid (4 nc, 16 h, 4 b).
// ---------------------------------------------------------------------------
#define KVT 8192   // one 64x64 fp16 tile

__global__ __launch_bounds__(128)
void kvmat_mma(const __half* __restrict__ k, const __half* __restrict__ v,
               float* __restrict__ kvp, float* __restrict__ kmp)
{
    __shared__ __align__(1024) char kvs_raw[4 * KVT];   // 2 bufs x (k|v)
    __shared__ float sks[2][64];
    const uint32_t sb = smem_u32(kvs_raw);

    const int tid = threadIdx.x;
    const int wid = tid >> 5, lid = tid & 31;
    const int nc = blockIdx.x, h = blockIdx.y, b = blockIdx.z;

    const size_t base = ((size_t)(b * 4096 + nc * 1024)) * 1024 + h * 64;

    auto load_sc = [&](int sc, int buf) {
        const uint32_t kb = sb + buf * 2 * KVT;
        #pragma unroll
        for (int i = 0; i < 4; ++i) {
            const int idx = i * 128 + tid;
            const int r = idx >> 3, c = idx & 7;
            const size_t go = base + (size_t)(sc * 64 + r) * 1024 + c * 8;
            const uint32_t so = SWZ128(r * 128 + c * 16);
            cpa16(kb + so, k + go);
            cpa16(kb + KVT + so, v + go);
        }
        asm volatile("cp.async.commit_group;" ::: "memory");
    };

    float acc[8][4];
    #pragma unroll
    for (int i = 0; i < 8; ++i)
        #pragma unroll
        for (int r = 0; r < 4; ++r) acc[i][r] = 0.f;
    float ks_acc = 0.f;

    // fused ksum mapping: chan e = tid&63, row group = tid>>6 (32 rows each)
    const int se = tid & 63;
    const int srg = tid >> 6;

    // ldmatrix.trans lane addressing: row = stored n-row, col = d (A) / e (B)
    const int trow  = ((lid >> 4) << 3) + (lid & 7);   // +0/8 n-row block
    const int tcolh = ((lid >> 3) & 1) << 3;           // +0/8 col halves

    load_sc(0, 0);
    for (int sc = 0; sc < 16; ++sc) {
        const int buf = sc & 1;
        if (sc < 15) {
            load_sc(sc + 1, buf ^ 1);
            asm volatile("cp.async.wait_group 1;" ::: "memory");
        } else {
            asm volatile("cp.async.wait_group 0;" ::: "memory");
        }
        __syncthreads();
        const uint32_t kb = sb + buf * 2 * KVT;
        #pragma unroll
        for (int ks = 0; ks < 4; ++ks) {
            uint32_t af[4], bf[4][4];
            ldmx4t(af, kb + SWZ128((ks * 16 + trow) * 128 +
                                   (wid * 16 + tcolh) * 2));
            #pragma unroll
            for (int nj = 0; nj < 4; ++nj)
                ldmx4t(bf[nj], kb + KVT + SWZ128((ks * 16 + trow) * 128 +
                                                 (nj * 16 + tcolh) * 2));
            #pragma unroll
            for (int ni = 0; ni < 8; ++ni) {
                const int nj = ni >> 1, s = ni & 1;
                mma16816(acc[ni], af, bf[nj][s], bf[nj][s + 2]);
            }
        }
        // fused k-column partial sums from the resident k tile
        #pragma unroll 8
        for (int rr = 0; rr < 32; ++rr) {
            const int row = srg * 32 + rr;
            const __half kv16 = *(const __half*)
                ((char*)kvs_raw + buf * 2 * KVT + SWZ128(row * 128 + se * 2));
            ks_acc += __half2float(kv16);
        }
        __syncthreads();
    }
    sks[srg][se] = ks_acc;

    const int qrow = lid >> 2;
    const int qcol = (lid & 3) * 2;
    float* kvo = kvp + (((size_t)(nc * 4 + b)) * 16 + h) * 4096;
    #pragma unroll
    for (int ni = 0; ni < 8; ++ni)
        #pragma unroll
        for (int half = 0; half < 2; ++half) {
            const int dm = wid * 16 + qrow + half * 8;
            *(float2*)(kvo + dm * 64 + ni * 8 + qcol) =
                make_float2(acc[ni][half * 2 + 0], acc[ni][half * 2 + 1]);
        }
    __syncthreads();
    if (tid < 64)
        kmp[(size_t)(nc * 4 + b) * 1024 + h * 64 + tid] =
            sks[0][tid] + sks[1][tid];
}

// ---------------------------------------------------------------------------
// reduce partials -> kv^T fp16 (scaled 1/4096) and kmean fp32
// ---------------------------------------------------------------------------
__global__ void reduce_kernel(const float* __restrict__ kvp,
                              const float* __restrict__ kmp,
                              __half* __restrict__ kvt, float* __restrict__ km)
{
    const int i = blockIdx.x * 256 + threadIdx.x;
    if (i < 262144) {
        float s = 0.f;
        #pragma unroll
        for (int nc = 0; nc < 4; ++nc) s += kvp[(size_t)nc * 262144 + i];
        const int d = (i >> 6) & 63, e = i & 63;
        kvt[(i & ~4095) + e * 64 + d] = __float2half_rn(s * (1.0f / 4096.0f));
    } else if (i < 262144 + 4096) {
        const int j = i - 262144;
        float s = 0.f;
        #pragma unroll
        for (int nc = 0; nc < 4; ++nc) s += kmp[nc * 4096 + j];
        km[j] = s * (1.0f / 4096.0f);
    }
}

// ---------------------------------------------------------------------------
// att via mma: per (b,h): att[n,e] = z_n * (q[n,:] @ kv[:,e]),
// A = q tile [128,64] fp16, B = kv^T [64,64] fp16. Writes fp16 into A16.
// ---------------------------------------------------------------------------
__global__ __launch_bounds__(128)
void att_mma(const __half* __restrict__ q, const __half* __restrict__ kvt,
             const float* __restrict__ km, __half* __restrict__ A16)
{
    __shared__ __align__(1024) char qs_raw[16384];   // 128x128B SW128
    __shared__ __align__(1024) char bs_raw[8192];    // 64x128B SW128
    __shared__ float kms[64];
    __shared__ float zs[128];

    const int tid = threadIdx.x;
    const int wid = tid >> 5, lid = tid & 31;
    const int bx = blockIdx.x, bh = blockIdx.y;
    const int b = bh >> 4, h = bh & 15;

    const uint32_t qsb = smem_u32(qs_raw);
    const uint32_t bsb = smem_u32(bs_raw);

    const size_t qbase = ((size_t)(b * 4096 + bx * 128)) * 1024 + h * 64;

    #pragma unroll
    for (int i = 0; i < 8; ++i) {
        const int idx = i * 128 + tid;
        const int r = idx >> 3, c = idx & 7;
        cpa16(qsb + SWZ128(r * 128 + c * 16), q + qbase + (size_t)r * 1024 + c * 8);
    }
    #pragma unroll
    for (int i = 0; i < 4; ++i) {
        const int idx = i * 128 + tid;
        const int r = idx >> 3, c = idx & 7;
        cpa16(bsb + SWZ128(r * 128 + c * 16), kvt + (size_t)bh * 4096 + r * 64 + c * 8);
    }
    asm volatile("cp.async.commit_group;" ::: "memory");

    if (tid < 16)
        ((float4*)kms)[tid] = ((const float4*)(km + b * 1024 + h * 64))[tid];
    __syncthreads();

    {
        const __half* qr = q + qbase + (size_t)tid * 1024;
        float zd = EPS;
        #pragma unroll
        for (int i = 0; i < 8; ++i) {
            const uint4 qd = *(const uint4*)(qr + i * 8);
            const __half2* qh = (const __half2*)&qd;
            #pragma unroll
            for (int j = 0; j < 4; ++j) {
                const float2 f = __half22float2(qh[j]);
                zd = fmaf(f.x, kms[i * 8 + 2 * j],     zd);
                zd = fmaf(f.y, kms[i * 8 + 2 * j + 1], zd);
            }
        }
        zs[tid] = 1.0f / zd;
    }

    float acc[2][8][4];
    #pragma unroll
    for (int i = 0; i < 2; ++i)
        #pragma unroll
        for (int j = 0; j < 8; ++j)
            #pragma unroll
            for (int r = 0; r < 4; ++r) acc[i][j][r] = 0.f;

    asm volatile("cp.async.wait_group 0;" ::: "memory");
    __syncthreads();

    const int wm = wid * 32;
    const int lr = lid & 15, lc = lid >> 4;
    #pragma unroll
    for (int ks = 0; ks < 4; ++ks) {
        uint32_t af[2][4], bf[4][4];
        #pragma unroll
        for (int mi = 0; mi < 2; ++mi)
            ldmx4(af[mi], qsb + SWZ128((wm + mi * 16 + lr) * 128 + ks * 32 + lc * 16));
        #pragma unroll
        for (int nj = 0; nj < 4; ++nj)
            ldmx4(bf[nj], bsb + SWZ128((nj * 16 + lr) * 128 + ks * 32 + lc * 16));
        #pragma unroll
        for (int mi = 0; mi < 2; ++mi)
            #pragma unroll
            for (int ni = 0; ni < 8; ++ni) {
                const int nj = ni >> 1, s = ni & 1;
                mma16816(acc[mi][ni], af[mi], bf[nj][s], bf[nj][s + 2]);
            }
    }

    const int qrow = lid >> 2;
    const int qcol = (lid & 3) * 2;
    __half* ob = A16 + qbase;
    #pragma unroll
    for (int mi = 0; mi < 2; ++mi)
        #pragma unroll
        for (int ni = 0; ni < 8; ++ni) {
            const int cn = ni * 8 + qcol;
            #pragma unroll
            for (int half = 0; half < 2; ++half) {
                const int rm = wm + mi * 16 + qrow + half * 8;
                const float z = zs[rm];
                *(__half2*)(ob + (size_t)rm * 1024 + cn) =
                    __floats2half2_rn(acc[mi][ni][half * 2 + 0] * z,
                                      acc[mi][ni][half * 2 + 1] * z);
            }
        }
}

// ---------------------------------------------------------------------------
// depthwise 5x5 SAME conv on fp16 v; A16 += conv (fp16 RMW)
// ---------------------------------------------------------------------------
__global__ __launch_bounds__(256)
void conv_kernel(const __half* __restrict__ v, const float* __restrict__ w,
                 const float* __restrict__ wb, __half* __restrict__ A16)
{
    const int e  = threadIdx.x & 63;
    const int xg = threadIdx.x >> 6;
    const int x  = blockIdx.x * 4 + xg;
    const int y0 = blockIdx.y * 8;
    const int bh = blockIdx.z;
    const int b = bh >> 4, h = bh & 15;

    float wgt[25];
    #pragma unroll
    for (int i = 0; i < 25; ++i) wgt[i] = w[e * 25 + i];
    const float bias = wb[e];

    const size_t cofs = (size_t)b * 4096 * 1024 + h * 64 + e;
    const __half* vb = v + cofs;
    __half* ab = A16 + cofs;

    float win[5][5];
    #pragma unroll
    for (int r = 0; r < 4; ++r) {
        const int yy = y0 - 2 + r;
        #pragma unroll
        for (int c = 0; c < 5; ++c) {
            const int xx = x - 2 + c;
            win[r][c] = (yy >= 0 && yy < 64 && xx >= 0 && xx < 64)
                        ? __half2float(vb[(size_t)(yy * 64 + xx) * 1024]) : 0.f;
        }
    }

    #pragma unroll
    for (int oy = 0; oy < 8; ++oy) {
        const int yy = y0 + oy + 2;
        #pragma unroll
        for (int c = 0; c < 5; ++c) {
            const int xx = x - 2 + c;
            win[4][c] = (yy < 64 && xx >= 0 && xx < 64)
                        ? __half2float(vb[(size_t)(yy * 64 + xx) * 1024]) : 0.f;
        }
        float acc = bias;
        #pragma unroll
        for (int r = 0; r < 5; ++r)
            #pragma unroll
            for (int c = 0; c < 5; ++c)
                acc = fmaf(win[r][c], wgt[r * 5 + c], acc);

        const size_t po = (size_t)((y0 + oy) * 64 + x) * 1024;
        ab[po] = __float2half_rn(__half2float(ab[po]) + acc);

        #pragma unroll
        for (int r = 0; r < 4; ++r)
            #pragma unroll
            for (int c = 0; c < 5; ++c) win[r][c] = win[r + 1][c];
    }
}

// ---------------------------------------------------------------------------
extern "C" void kernel_launch(void* const* d_in, const int* in_sizes, int n_in,
                              void* d_out, int out_size)
{
    const float* x     = (const float*)d_in[0];
    const float* Wq    = (const float*)d_in[1];
    const float* Wkv   = (const float*)d_in[2];
    const float* Wproj = (const float*)d_in[3];
    const float* bproj = (const float*)d_in[4];
    const float* dwc_w = (const float*)d_in[5];
    const float* dwc_b = (const float*)d_in[6];
    float* out = (float*)d_out;

    float *km, *kvp, *kmp;
    __half *q16, *k16, *v16, *a16, *w16, *kvt16;
    cudaGetSymbolAddress((void**)&q16,   g_q16);
    cudaGetSymbolAddress((void**)&k16,   g_k16);
    cudaGetSymbolAddress((void**)&v16,   g_v16);
    cudaGetSymbolAddress((void**)&km,    g_kmean);
    cudaGetSymbolAddress((void**)&kvt16, g_kvt16);
    cudaGetSymbolAddress((void**)&kvp,   g_kvp);
    cudaGetSymbolAddress((void**)&kmp,   g_kmp);
    cudaGetSymbolAddress((void**)&a16,   g_a16);
    cudaGetSymbolAddress((void**)&w16,   g_w16);

    cudaFuncSetAttribute(mma_gemm, cudaFuncAttributeMaxDynamicSharedMemorySize,
                         NSTAGE * STG);

    const size_t smem = NSTAGE * STG;

    // launches 1-3, then the big GEMM as launch #4 (ncu capture target)
    acvt<<<16384, 256>>>((const float4*)x, (__half2*)a16, 4194304);
    wtcvt<<<dim3(32, 32), dim3(32, 8)>>>(Wq,  w16,           1024, 1024);
    wtcvt<<<dim3(64, 32), dim3(32, 8)>>>(Wkv, w16 + 1048576, 1024, 2048);

    // merged q/k/v GEMM: N=3072 -> fp16 q,k,v   (launch #4)
    mma_gemm<<<dim3(24, 128), 256, smem>>>(a16, w16, q16, k16, v16, nullptr, 0);

    // Wproj convert (only needed by the final GEMM)
    wtcvt<<<dim3(32, 32), dim3(32, 8)>>>(Wproj, w16 + 3145728, 1024, 1024);

    kvmat_mma<<<dim3(4, 16, 4), 128>>>(k16, v16, kvp, kmp);
    reduce_kernel<<<1040, 256>>>(kvp, kmp, kvt16, km);
    att_mma<<<dim3(32, 64), 128>>>(q16, kvt16, km, a16);
    conv_kernel<<<dim3(16, 8, 64), 256>>>(v16, dwc_w, dwc_b, a16);

    // out = (att+conv) @ Wproj + bproj  (fp32 out)
    mma_gemm<<<dim3(8, 128), 256, smem>>>(a16, w16 + 3145728, out, nullptr,
                                          nullptr, bproj, 1);
}